// round 1
// baseline (speedup 1.0000x reference)
#include <cuda_runtime.h>
#include <math.h>

#define BB 4
#define TT 4096
#define EE 1024
#define DD 64
#define MM (BB*TT)

// Scratch for q, k, v projections (allocation-free rule: device globals).
__device__ float g_q[MM*DD];
__device__ float g_k[MM*DD];
__device__ float g_v[MM*DD];

// ---------------------------------------------------------------------------
// QKV projection: [16384 x 1024] @ [1024 x 192] (q|k|v concatenated) + bias
// Block tile 128(M) x 192(N), K-step 32. 512 threads, 8x6 micro-tile.
// ---------------------------------------------------------------------------
__global__ __launch_bounds__(512) void qkv_kernel(
    const float* __restrict__ X,
    const float* __restrict__ Wq, const float* __restrict__ bq,
    const float* __restrict__ Wk, const float* __restrict__ bk,
    const float* __restrict__ Wv, const float* __restrict__ bv)
{
    __shared__ float Xs[128][32];   // 16 KB
    __shared__ float Ws[32][192];   // 24 KB

    const int tid = threadIdx.x;
    const int tx  = tid & 31;       // N direction (32 thread-cols)
    const int ty  = tid >> 5;       // M direction (16 thread-rows)
    const int m0  = blockIdx.x * 128;

    float acc[8][6];
#pragma unroll
    for (int i = 0; i < 8; i++)
#pragma unroll
        for (int j = 0; j < 6; j++) acc[i][j] = 0.f;

    for (int k0 = 0; k0 < EE; k0 += 32) {
        // X tile: 128 rows x 32 cols = 1024 float4, 2 per thread (coalesced)
#pragma unroll
        for (int i = 0; i < 2; i++) {
            int f = tid + i * 512;
            int row = f >> 3, c4 = (f & 7) * 4;
            *(float4*)&Xs[row][c4] =
                *(const float4*)&X[(size_t)(m0 + row) * EE + k0 + c4];
        }
        // W tiles: 32 x 64 per matrix = 512 float4 each, 1 per thread per matrix
        {
            int row = tid >> 4, c4 = (tid & 15) * 4;
            const float4 aq = *(const float4*)&Wq[(size_t)(k0 + row) * DD + c4];
            const float4 ak = *(const float4*)&Wk[(size_t)(k0 + row) * DD + c4];
            const float4 av = *(const float4*)&Wv[(size_t)(k0 + row) * DD + c4];
            *(float4*)&Ws[row][      c4] = aq;
            *(float4*)&Ws[row][ 64 + c4] = ak;
            *(float4*)&Ws[row][128 + c4] = av;
        }
        __syncthreads();

#pragma unroll
        for (int kk = 0; kk < 32; kk++) {
            float x[8], w[6];
#pragma unroll
            for (int i = 0; i < 8; i++) x[i] = Xs[ty * 8 + i][kk];  // broadcast
#pragma unroll
            for (int j = 0; j < 6; j++) w[j] = Ws[kk][tx + 32 * j]; // conflict-free
#pragma unroll
            for (int i = 0; i < 8; i++)
#pragma unroll
                for (int j = 0; j < 6; j++)
                    acc[i][j] = fmaf(x[i], w[j], acc[i][j]);
        }
        __syncthreads();
    }

    // Epilogue: bias + store to q/k/v scratch. mat = j>>1, col = tx + 32*(j&1)
#pragma unroll
    for (int j = 0; j < 6; j++) {
        const int mat  = j >> 1;
        const int cold = tx + 32 * (j & 1);
        const float* bp = (mat == 0) ? bq : (mat == 1) ? bk : bv;
        float* dst      = (mat == 0) ? g_q : (mat == 1) ? g_k : g_v;
        const float bias = bp[cold];
#pragma unroll
        for (int i = 0; i < 8; i++)
            dst[(size_t)(m0 + ty * 8 + i) * DD + cold] = acc[i][j] + bias;
    }
}

// ---------------------------------------------------------------------------
// Flash attention, causal, fp32. Block = 64 q-rows, 8 warps x 8 rows.
// Each block processes q-tile pair (qx, 63-qx) -> constant 65 kv-iterations.
// Shared rows padded to 68 floats (16B-aligned, conflict-free LDS.128).
// ---------------------------------------------------------------------------
#define PAD 68
#define ATTN_SMEM (4 * 64 * PAD * 4)   // Qs,Ks,Vs,Ps = 69632 bytes

__global__ __launch_bounds__(256) void attn_kernel(float* __restrict__ out)
{
    extern __shared__ float smem[];
    float (*Qs)[PAD] = (float(*)[PAD])(smem);
    float (*Ks)[PAD] = (float(*)[PAD])(smem + 1 * 64 * PAD);
    float (*Vs)[PAD] = (float(*)[PAD])(smem + 2 * 64 * PAD);
    float (*Ps)[PAD] = (float(*)[PAD])(smem + 3 * 64 * PAD);

    const int tid  = threadIdx.x;
    const int warp = tid >> 5;
    const int lane = tid & 31;
    const int b    = blockIdx.y;

    const float* qbase = g_q + (size_t)b * TT * DD;
    const float* kbase = g_k + (size_t)b * TT * DD;
    const float* vbase = g_v + (size_t)b * TT * DD;

    for (int qsel = 0; qsel < 2; qsel++) {
        const int qt = qsel ? (63 - (int)blockIdx.x) : (int)blockIdx.x;

        __syncthreads();  // previous pass fully done with Qs
        // Load Q tile: 64x64 = 1024 float4, 4 per thread
#pragma unroll
        for (int i = 0; i < 4; i++) {
            int f = tid + i * 256;
            int row = f >> 4, c4 = (f & 15) * 4;
            *(float4*)&Qs[row][c4] =
                *(const float4*)&qbase[(size_t)(qt * 64 + row) * DD + c4];
        }

        float o0[8], o1[8], mr[8], lr[8];
#pragma unroll
        for (int r = 0; r < 8; r++) {
            o0[r] = 0.f; o1[r] = 0.f; mr[r] = -3.0e38f; lr[r] = 0.f;
        }

        for (int j = 0; j <= qt; j++) {
            __syncthreads();  // everyone done with previous Ks/Vs (and Q visible)
#pragma unroll
            for (int i = 0; i < 4; i++) {
                int f = tid + i * 256;
                int row = f >> 4, c4 = (f & 15) * 4;
                *(float4*)&Ks[row][c4] =
                    *(const float4*)&kbase[(size_t)(j * 64 + row) * DD + c4];
                *(float4*)&Vs[row][c4] =
                    *(const float4*)&vbase[(size_t)(j * 64 + row) * DD + c4];
            }
            __syncthreads();

            // --- GEMM1: S[8 rows][cols lane, lane+32] = Q . K^T ---
            float s0[8], s1[8];
#pragma unroll
            for (int r = 0; r < 8; r++) { s0[r] = 0.f; s1[r] = 0.f; }
#pragma unroll 4
            for (int d4 = 0; d4 < 16; d4++) {
                float4 k0 = *(float4*)&Ks[lane     ][d4 * 4];
                float4 k1 = *(float4*)&Ks[lane + 32][d4 * 4];
#pragma unroll
                for (int r = 0; r < 8; r++) {
                    float4 q = *(float4*)&Qs[warp * 8 + r][d4 * 4];
                    s0[r] = fmaf(q.x, k0.x, fmaf(q.y, k0.y,
                             fmaf(q.z, k0.z, fmaf(q.w, k0.w, s0[r]))));
                    s1[r] = fmaf(q.x, k1.x, fmaf(q.y, k1.y,
                             fmaf(q.z, k1.z, fmaf(q.w, k1.w, s1[r]))));
                }
            }

            const bool diag = (j == qt);
#pragma unroll
            for (int r = 0; r < 8; r++) {
                float a0 = s0[r] * 0.125f;   // 1/sqrt(64)
                float a1 = s1[r] * 0.125f;
                if (diag) {
                    int rg = qt * 64 + warp * 8 + r;
                    if (j * 64 + lane      > rg) a0 = -1e30f;
                    if (j * 64 + lane + 32 > rg) a1 = -1e30f;
                }
                float mx = fmaxf(a0, a1);
#pragma unroll
                for (int off = 16; off; off >>= 1)
                    mx = fmaxf(mx, __shfl_xor_sync(0xffffffffu, mx, off));
                float mnew  = fmaxf(mr[r], mx);
                float alpha = __expf(mr[r] - mnew);
                float p0 = __expf(a0 - mnew);
                float p1 = __expf(a1 - mnew);
                float ps = p0 + p1;
#pragma unroll
                for (int off = 16; off; off >>= 1)
                    ps += __shfl_xor_sync(0xffffffffu, ps, off);
                lr[r] = lr[r] * alpha + ps;
                mr[r] = mnew;
                o0[r] *= alpha;
                o1[r] *= alpha;
                Ps[warp * 8 + r][lane     ] = p0;
                Ps[warp * 8 + r][lane + 32] = p1;
            }
            __syncwarp();  // P rows are warp-private; make them visible in-warp

            // --- GEMM2: O[8 rows][cols lane, lane+32] += P @ V ---
#pragma unroll 4
            for (int c4 = 0; c4 < 16; c4++) {
                float4 p[8];
#pragma unroll
                for (int r = 0; r < 8; r++)
                    p[r] = *(float4*)&Ps[warp * 8 + r][c4 * 4];  // broadcast
#pragma unroll
                for (int i = 0; i < 4; i++) {
                    float v0 = Vs[c4 * 4 + i][lane     ];  // bank = 4c+lane, conflict-free
                    float v1 = Vs[c4 * 4 + i][lane + 32];
#pragma unroll
                    for (int r = 0; r < 8; r++) {
                        float pc = (i == 0) ? p[r].x : (i == 1) ? p[r].y
                                 : (i == 2) ? p[r].z : p[r].w;
                        o0[r] = fmaf(pc, v0, o0[r]);
                        o1[r] = fmaf(pc, v1, o1[r]);
                    }
                }
            }
        }

        // Epilogue: O /= l, write [B,T,D]
#pragma unroll
        for (int r = 0; r < 8; r++) {
            float inv = 1.f / lr[r];
            size_t orow = ((size_t)b * TT + qt * 64 + warp * 8 + r) * DD;
            out[orow + lane     ] = o0[r] * inv;
            out[orow + lane + 32] = o1[r] * inv;
        }
    }
}

// ---------------------------------------------------------------------------
extern "C" void kernel_launch(void* const* d_in, const int* in_sizes, int n_in,
                              void* d_out, int out_size)
{
    const float* X  = (const float*)d_in[0];
    const float* Wq = (const float*)d_in[1];
    const float* bq = (const float*)d_in[2];
    const float* Wk = (const float*)d_in[3];
    const float* bk = (const float*)d_in[4];
    const float* Wv = (const float*)d_in[5];
    const float* bv = (const float*)d_in[6];
    float* out = (float*)d_out;

    qkv_kernel<<<MM / 128, 512>>>(X, Wq, bq, Wk, bk, Wv, bv);

    // Host-side attribute set (not a stream op; capture-safe, idempotent).
    cudaFuncSetAttribute(attn_kernel,
                         cudaFuncAttributeMaxDynamicSharedMemorySize, ATTN_SMEM);
    attn_kernel<<<dim3(32, BB), 256, ATTN_SMEM>>>(out);
}

// round 3
// speedup vs baseline: 1.3188x; 1.3188x over previous
#include <cuda_runtime.h>
#include <cuda_bf16.h>
#include <cstdint>
#include <math.h>

#define BB 4
#define TT 4096
#define EE 1024
#define DD 64
#define MM (BB*TT)

// ---------------------------------------------------------------------------
// Device scratch (allocation-free rule: device globals)
// ---------------------------------------------------------------------------
__device__ float g_q[MM*DD];
__device__ float g_k[MM*DD];
__device__ float g_v[MM*DD];

// Pre-split, pre-swizzled bf16 W tiles: [16 k-chunks][192 rows][128 bytes]
// Row n = mat*64 + d holds Wt[n][k] = W[k][d] for 64 k-values (bf16), SW128.
#define WCHUNK_BYTES (192*128)
__device__ unsigned char g_whi[16*WCHUNK_BYTES];
__device__ unsigned char g_wlo[16*WCHUNK_BYTES];

// ---------------------------------------------------------------------------
// Helpers
// ---------------------------------------------------------------------------
#define DEVINL __device__ __forceinline__

DEVINL uint32_t smem_u32(const void* p) {
    uint32_t a;
    asm("{ .reg .u64 t; cvta.to.shared.u64 t, %1; cvt.u32.u64 %0, t; }"
        : "=r"(a) : "l"(p));
    return a;
}

#define SWZ128(o) ((o) ^ (((o) >> 3) & 0x70))

#define CP_ASYNC16(dst, src) \
    asm volatile("cp.async.cg.shared.global [%0], [%1], 16;" \
                 :: "r"(dst), "l"(src) : "memory")
#define CP_COMMIT() asm volatile("cp.async.commit_group;" ::: "memory")
#define CP_WAIT0()  asm volatile("cp.async.wait_group 0;"  ::: "memory")

DEVINL uint32_t pack_bf16x2(__nv_bfloat16 a, __nv_bfloat16 b) {
    return (uint32_t)__bfloat16_as_ushort(a) |
           ((uint32_t)__bfloat16_as_ushort(b) << 16);
}
DEVINL void split_bf16(float x, __nv_bfloat16& h, __nv_bfloat16& l) {
    h = __float2bfloat16(x);
    l = __float2bfloat16(x - __bfloat162float(h));
}

DEVINL void ldsm_x4(uint32_t r[4], uint32_t addr) {
    asm volatile("ldmatrix.sync.aligned.m8n8.x4.shared.b16 {%0,%1,%2,%3}, [%4];"
        : "=r"(r[0]), "=r"(r[1]), "=r"(r[2]), "=r"(r[3]) : "r"(addr));
}
DEVINL void ldsm_x2(uint32_t r[2], uint32_t addr) {
    asm volatile("ldmatrix.sync.aligned.m8n8.x2.shared.b16 {%0,%1}, [%2];"
        : "=r"(r[0]), "=r"(r[1]) : "r"(addr));
}
// D = A(16x16, row) * B(16x8, col) + D,  bf16 in / f32 accum
DEVINL void mma16816(float c[4], const uint32_t a[4], const uint32_t b[2]) {
    asm volatile(
        "mma.sync.aligned.m16n8k16.row.col.f32.bf16.bf16.f32 "
        "{%0,%1,%2,%3}, {%4,%5,%6,%7}, {%8,%9}, {%0,%1,%2,%3};"
        : "+f"(c[0]), "+f"(c[1]), "+f"(c[2]), "+f"(c[3])
        : "r"(a[0]), "r"(a[1]), "r"(a[2]), "r"(a[3]), "r"(b[0]), "r"(b[1]));
}

// ---------------------------------------------------------------------------
// W prep: split W into bf16 hi/lo, transposed (rows n, k contiguous), SW128.
// ---------------------------------------------------------------------------
__global__ void w_prep(const float* __restrict__ Wq,
                       const float* __restrict__ Wk,
                       const float* __restrict__ Wv) {
    const int c = blockIdx.x;  // k-chunk 0..15
    for (int it = threadIdx.x; it < 1536; it += 256) {
        int n = it % 192;         // B row
        int g = it / 192;         // kk group of 8
        int mat = n >> 6, d = n & 63;
        const float* Wm = (mat == 0) ? Wq : (mat == 1) ? Wk : Wv;
        int kk0 = g * 8;
        uint32_t hi[4], lo[4];
#pragma unroll
        for (int j = 0; j < 4; j++) {
            __nv_bfloat16 h0, l0, h1, l1;
            split_bf16(Wm[(size_t)(c*64 + kk0 + 2*j    ) * 64 + d], h0, l0);
            split_bf16(Wm[(size_t)(c*64 + kk0 + 2*j + 1) * 64 + d], h1, l1);
            hi[j] = pack_bf16x2(h0, h1);
            lo[j] = pack_bf16x2(l0, l1);
        }
        uint32_t boff = (uint32_t)n * 128 + (uint32_t)kk0 * 2;  // 16B aligned
        uint32_t sw   = SWZ128(boff);
        *(uint4*)(g_whi + (size_t)c * WCHUNK_BYTES + sw) = make_uint4(hi[0], hi[1], hi[2], hi[3]);
        *(uint4*)(g_wlo + (size_t)c * WCHUNK_BYTES + sw) = make_uint4(lo[0], lo[1], lo[2], lo[3]);
    }
}

// ---------------------------------------------------------------------------
// QKV via mma.sync bf16-split.  CTA tile M=64, N=192 (q|k|v), K chunks of 64.
// 8 warps, warp tile 64(M) x 24(N) = 4 m-tiles x 3 n-tiles of m16n8k16.
// Double-buffered smem, cp.async W, LDG-X-before-MMA overlap.
// ---------------------------------------------------------------------------
#define QB_A_HI 0
#define QB_A_LO 8192
#define QB_B_HI 16384
#define QB_B_LO 40960
#define QB_STRIDE 65536
#define QKV_SMEM (2*QB_STRIDE)   // 131072

__global__ __launch_bounds__(256, 1) void qkv_mma(
    const float* __restrict__ X,
    const float* __restrict__ bq, const float* __restrict__ bk,
    const float* __restrict__ bv)
{
    extern __shared__ __align__(1024) unsigned char sm[];
    const uint32_t sb = smem_u32(sm);
    const int tid  = threadIdx.x;
    const int warp = tid >> 5;
    const int lane = tid & 31;
    const int m0   = blockIdx.x * 64;
    const int wbase = warp * 24;

    // ldmatrix per-lane row/col constants
    const int rA = (lane & 7) | (((lane >> 3) & 1) << 3);  // A row within 16
    const int uA = lane >> 4;                              // A 16B-unit sel
    const int rB = lane & 7;                               // B row within 8
    const int uB = (lane >> 3) & 1;                        // B 16B-unit sel
    const uint32_t swA = (uint32_t)(rA & 7) << 4;
    const uint32_t swB = (uint32_t)(rB & 7) << 4;

    float acc[4][3][4];
#pragma unroll
    for (int mt = 0; mt < 4; mt++)
#pragma unroll
        for (int nt = 0; nt < 3; nt++)
#pragma unroll
            for (int i = 0; i < 4; i++) acc[mt][nt][i] = 0.f;

    // ---- prologue: stage chunk 0 into buffer 0 ----
    {
        const unsigned char* wh = g_whi;
        const unsigned char* wl = g_wlo;
#pragma unroll
        for (int j = 0; j < 6; j++) {
            int f = tid + 256 * j;
            CP_ASYNC16(sb + QB_B_HI + f * 16, wh + (size_t)f * 16);
            CP_ASYNC16(sb + QB_B_LO + f * 16, wl + (size_t)f * 16);
        }
        CP_COMMIT();
#pragma unroll
        for (int i = 0; i < 4; i++) {
            int f = tid + 256 * i;
            int row = f >> 4, c4 = (f & 15) * 4;
            float4 x = *(const float4*)&X[(size_t)(m0 + row) * EE + c4];
            __nv_bfloat16 h0,l0,h1,l1,h2,l2,h3,l3;
            split_bf16(x.x, h0, l0); split_bf16(x.y, h1, l1);
            split_bf16(x.z, h2, l2); split_bf16(x.w, h3, l3);
            uint32_t off = SWZ128((uint32_t)row * 128 + (uint32_t)c4 * 2);
            *(uint2*)(sm + QB_A_HI + off) = make_uint2(pack_bf16x2(h0,h1), pack_bf16x2(h2,h3));
            *(uint2*)(sm + QB_A_LO + off) = make_uint2(pack_bf16x2(l0,l1), pack_bf16x2(l2,l3));
        }
        CP_WAIT0();
        __syncthreads();
    }

    for (int c = 0; c < 16; c++) {
        const uint32_t bufc = sb + (uint32_t)(c & 1) * QB_STRIDE;
        unsigned char* bn   = sm + ((c + 1) & 1) * QB_STRIDE;
        const uint32_t bufnu = sb + (uint32_t)((c + 1) & 1) * QB_STRIDE;
        const bool hasNext = (c < 15);

        float4 xr[4];
        if (hasNext) {
            const unsigned char* wh = g_whi + (size_t)(c + 1) * WCHUNK_BYTES;
            const unsigned char* wl = g_wlo + (size_t)(c + 1) * WCHUNK_BYTES;
#pragma unroll
            for (int j = 0; j < 6; j++) {
                int f = tid + 256 * j;
                CP_ASYNC16(bufnu + QB_B_HI + f * 16, wh + (size_t)f * 16);
                CP_ASYNC16(bufnu + QB_B_LO + f * 16, wl + (size_t)f * 16);
            }
            CP_COMMIT();
#pragma unroll
            for (int i = 0; i < 4; i++) {
                int f = tid + 256 * i;
                int row = f >> 4, c4 = (f & 15) * 4;
                xr[i] = *(const float4*)&X[(size_t)(m0 + row) * EE + (c + 1) * 64 + c4];
            }
        }

        // ---- compute on bufc: 4 k16 steps ----
#pragma unroll
        for (int kk = 0; kk < 4; kk++) {
            uint32_t ah[4][4], al[4][4];
#pragma unroll
            for (int mt = 0; mt < 4; mt++) {
                uint32_t ra = bufc + QB_A_HI + (uint32_t)(16*mt + rA) * 128
                            + (((uint32_t)(2*kk + uA) * 16) ^ swA);
                ldsm_x4(ah[mt], ra);
                ldsm_x4(al[mt], ra + (QB_A_LO - QB_A_HI));
            }
            uint32_t bh[3][2], bl[3][2];
#pragma unroll
            for (int nt = 0; nt < 3; nt++) {
                uint32_t rb = bufc + QB_B_HI + (uint32_t)(wbase + 8*nt + rB) * 128
                            + (((uint32_t)(2*kk + uB) * 16) ^ swB);
                ldsm_x2(bh[nt], rb);
                ldsm_x2(bl[nt], rb + (QB_B_LO - QB_B_HI));
            }
#pragma unroll
            for (int mt = 0; mt < 4; mt++)
#pragma unroll
                for (int nt = 0; nt < 3; nt++) {
                    mma16816(acc[mt][nt], ah[mt], bh[nt]);
                    mma16816(acc[mt][nt], ah[mt], bl[nt]);
                    mma16816(acc[mt][nt], al[mt], bh[nt]);
                }
        }

        if (hasNext) {
#pragma unroll
            for (int i = 0; i < 4; i++) {
                int f = tid + 256 * i;
                int row = f >> 4, c4 = (f & 15) * 4;
                __nv_bfloat16 h0,l0,h1,l1,h2,l2,h3,l3;
                split_bf16(xr[i].x, h0, l0); split_bf16(xr[i].y, h1, l1);
                split_bf16(xr[i].z, h2, l2); split_bf16(xr[i].w, h3, l3);
                uint32_t off = SWZ128((uint32_t)row * 128 + (uint32_t)c4 * 2);
                *(uint2*)(bn + QB_A_HI + off) = make_uint2(pack_bf16x2(h0,h1), pack_bf16x2(h2,h3));
                *(uint2*)(bn + QB_A_LO + off) = make_uint2(pack_bf16x2(l0,l1), pack_bf16x2(l2,l3));
            }
            CP_WAIT0();
        }
        __syncthreads();
    }

    // ---- epilogue: bias + store to q/k/v scratch ----
    const int gid = lane >> 2, tig = lane & 3;
#pragma unroll
    for (int mt = 0; mt < 4; mt++) {
#pragma unroll
        for (int nt = 0; nt < 3; nt++) {
            const int col0 = wbase + 8 * nt;          // 8-aligned, never crosses 64
            const int mat  = col0 >> 6;
            const int d0   = (col0 & 63) + 2 * tig;
            const float* bp = (mat == 0) ? bq : (mat == 1) ? bk : bv;
            float* dst = (mat == 0) ? g_q : (mat == 1) ? g_k : g_v;
            const float b0v = bp[d0], b1v = bp[d0 + 1];
            const int row0 = m0 + 16 * mt + gid;
            float2 v0 = make_float2(acc[mt][nt][0] + b0v, acc[mt][nt][1] + b1v);
            float2 v1 = make_float2(acc[mt][nt][2] + b0v, acc[mt][nt][3] + b1v);
            *(float2*)&dst[(size_t)row0 * DD + d0]       = v0;
            *(float2*)&dst[(size_t)(row0 + 8) * DD + d0] = v1;
        }
    }
}

// ---------------------------------------------------------------------------
// Flash attention, causal, fp32 FFMA. q-tile 64, kv-tile 128.
// cp.async double-buffered K/V, one __syncthreads per iteration.
// Pair (qt, 63-qt) -> constant 33 kv-iterations per block. Grid 32x4.
// ---------------------------------------------------------------------------
#define PADK 68
#define PADP 132
#define F_Q  0
#define F_K0 (F_Q + 64*PADK)
#define F_K1 (F_K0 + 128*PADK)
#define F_V0 (F_K1 + 128*PADK)
#define F_V1 (F_V0 + 128*PADK)
#define F_P  (F_V1 + 128*PADK)
#define ATTN_SMEM ((F_P + 64*PADP) * 4)  // 190464 bytes

__global__ __launch_bounds__(256) void attn_kernel(float* __restrict__ out)
{
    extern __shared__ __align__(1024) unsigned char dynsm[];
    float* smf = (float*)dynsm;
    float* Qs = smf + F_Q;
    float* Kbuf[2] = { smf + F_K0, smf + F_K1 };
    float* Vbuf[2] = { smf + F_V0, smf + F_V1 };
    float* Ps = smf + F_P;
    const uint32_t sbase = smem_u32(smf);
    const uint32_t ku[2] = { sbase + F_K0*4, sbase + F_K1*4 };
    const uint32_t vu[2] = { sbase + F_V0*4, sbase + F_V1*4 };

    const int tid  = threadIdx.x;
    const int warp = tid >> 5;
    const int lane = tid & 31;
    const int b    = blockIdx.y;

    const float* qbase = g_q + (size_t)b * TT * DD;
    const float* kbase = g_k + (size_t)b * TT * DD;
    const float* vbase = g_v + (size_t)b * TT * DD;

    const int cp_row[8] = { (tid)>>4, (tid+256)>>4, (tid+512)>>4, (tid+768)>>4,
                            (tid+1024)>>4, (tid+1280)>>4, (tid+1536)>>4, (tid+1792)>>4 };
    const int cp_c4 = (tid & 15) * 4;

    for (int qsel = 0; qsel < 2; qsel++) {
        const int qt = qsel ? (63 - (int)blockIdx.x) : (int)blockIdx.x;
        const int jt = (qt * 64 + 63) >> 7;   // last kv-128 tile index

        __syncthreads();  // previous pass done with all smem
#pragma unroll
        for (int i = 0; i < 4; i++) {
            int f = tid + i * 256;
            int row = f >> 4, c4 = (f & 15) * 4;
            *(float4*)&Qs[row * PADK + c4] =
                *(const float4*)&qbase[(size_t)(qt * 64 + row) * DD + c4];
        }
        {
#pragma unroll
            for (int i = 0; i < 8; i++) {
                int row = cp_row[i];
                uint32_t off = ((uint32_t)row * PADK + cp_c4) * 4;
                CP_ASYNC16(ku[0] + off, &kbase[(size_t)row * DD + cp_c4]);
                CP_ASYNC16(vu[0] + off, &vbase[(size_t)row * DD + cp_c4]);
            }
            CP_COMMIT();
        }

        float o0[8], o1[8], mr[8], lr[8];
#pragma unroll
        for (int r = 0; r < 8; r++) { o0[r]=0.f; o1[r]=0.f; mr[r]=-3.0e38f; lr[r]=0.f; }

        for (int j = 0; j <= jt; j++) {
            CP_WAIT0();
            __syncthreads();
            const int cur = j & 1;
            if (j < jt) {
                const size_t gro = (size_t)(j + 1) * 128 * DD;
#pragma unroll
                for (int i = 0; i < 8; i++) {
                    int row = cp_row[i];
                    uint32_t off = ((uint32_t)row * PADK + cp_c4) * 4;
                    CP_ASYNC16(ku[cur^1] + off, &kbase[gro + (size_t)row * DD + cp_c4]);
                    CP_ASYNC16(vu[cur^1] + off, &vbase[gro + (size_t)row * DD + cp_c4]);
                }
                CP_COMMIT();
            }
            const float* K = Kbuf[cur];
            const float* V = Vbuf[cur];

            // --- GEMM1: S = Q . K^T (cols lane+32c, c=0..3) ---
            float s0[8], s1[8], s2[8], s3[8];
#pragma unroll
            for (int r = 0; r < 8; r++) { s0[r]=0.f; s1[r]=0.f; s2[r]=0.f; s3[r]=0.f; }
#pragma unroll 4
            for (int d4 = 0; d4 < 16; d4++) {
                float4 k0 = *(float4*)&K[(lane      ) * PADK + d4 * 4];
                float4 k1 = *(float4*)&K[(lane + 32 ) * PADK + d4 * 4];
                float4 k2 = *(float4*)&K[(lane + 64 ) * PADK + d4 * 4];
                float4 k3 = *(float4*)&K[(lane + 96 ) * PADK + d4 * 4];
#pragma unroll
                for (int r = 0; r < 8; r++) {
                    float4 q = *(float4*)&Qs[(warp * 8 + r) * PADK + d4 * 4];
                    s0[r] = fmaf(q.x,k0.x, fmaf(q.y,k0.y, fmaf(q.z,k0.z, fmaf(q.w,k0.w, s0[r]))));
                    s1[r] = fmaf(q.x,k1.x, fmaf(q.y,k1.y, fmaf(q.z,k1.z, fmaf(q.w,k1.w, s1[r]))));
                    s2[r] = fmaf(q.x,k2.x, fmaf(q.y,k2.y, fmaf(q.z,k2.z, fmaf(q.w,k2.w, s2[r]))));
                    s3[r] = fmaf(q.x,k3.x, fmaf(q.y,k3.y, fmaf(q.z,k3.z, fmaf(q.w,k3.w, s3[r]))));
                }
            }

            const bool dg = (j == jt);
#pragma unroll
            for (int r = 0; r < 8; r++) {
                float a0 = s0[r]*0.125f, a1 = s1[r]*0.125f, a2 = s2[r]*0.125f, a3 = s3[r]*0.125f;
                if (dg) {
                    int rg = qt * 64 + warp * 8 + r;
                    int c0 = j * 128 + lane;
                    if (c0      > rg) a0 = -1e30f;
                    if (c0 + 32 > rg) a1 = -1e30f;
                    if (c0 + 64 > rg) a2 = -1e30f;
                    if (c0 + 96 > rg) a3 = -1e30f;
                }
                float mx = fmaxf(fmaxf(a0, a1), fmaxf(a2, a3));
#pragma unroll
                for (int off = 16; off; off >>= 1)
                    mx = fmaxf(mx, __shfl_xor_sync(0xffffffffu, mx, off));
                float mnew  = fmaxf(mr[r], mx);
                float alpha = __expf(mr[r] - mnew);
                float p0 = __expf(a0 - mnew), p1 = __expf(a1 - mnew);
                float p2 = __expf(a2 - mnew), p3 = __expf(a3 - mnew);
                float ps = (p0 + p1) + (p2 + p3);
#pragma unroll
                for (int off = 16; off; off >>= 1)
                    ps += __shfl_xor_sync(0xffffffffu, ps, off);
                lr[r] = lr[r] * alpha + ps;
                mr[r] = mnew;
                o0[r] *= alpha;
                o1[r] *= alpha;
                float* prow = &Ps[(warp * 8 + r) * PADP];
                prow[lane]      = p0;
                prow[lane + 32] = p1;
                prow[lane + 64] = p2;
                prow[lane + 96] = p3;
            }
            __syncwarp();  // P rows are warp-private

            // --- GEMM2: O += P @ V ---
#pragma unroll 4
            for (int c4 = 0; c4 < 32; c4++) {
                float4 p[8];
#pragma unroll
                for (int r = 0; r < 8; r++)
                    p[r] = *(float4*)&Ps[(warp * 8 + r) * PADP + c4 * 4];
#pragma unroll
                for (int i = 0; i < 4; i++) {
                    float v0 = V[(c4 * 4 + i) * PADK + lane];
                    float v1 = V[(c4 * 4 + i) * PADK + lane + 32];
#pragma unroll
                    for (int r = 0; r < 8; r++) {
                        float pc = (i == 0) ? p[r].x : (i == 1) ? p[r].y
                                 : (i == 2) ? p[r].z : p[r].w;
                        o0[r] = fmaf(pc, v0, o0[r]);
                        o1[r] = fmaf(pc, v1, o1[r]);
                    }
                }
            }
        }

        // Epilogue
#pragma unroll
        for (int r = 0; r < 8; r++) {
            float inv = 1.f / lr[r];
            size_t orow = ((size_t)b * TT + qt * 64 + warp * 8 + r) * DD;
            out[orow + lane]      = o0[r] * inv;
            out[orow + lane + 32] = o1[r] * inv;
        }
    }
}

// ---------------------------------------------------------------------------
extern "C" void kernel_launch(void* const* d_in, const int* in_sizes, int n_in,
                              void* d_out, int out_size)
{
    const float* X  = (const float*)d_in[0];
    const float* Wq = (const float*)d_in[1];
    const float* bq = (const float*)d_in[2];
    const float* Wk = (const float*)d_in[3];
    const float* bk = (const float*)d_in[4];
    const float* Wv = (const float*)d_in[5];
    const float* bv = (const float*)d_in[6];
    float* out = (float*)d_out;

    w_prep<<<16, 256>>>(Wq, Wk, Wv);

    cudaFuncSetAttribute(qkv_mma, cudaFuncAttributeMaxDynamicSharedMemorySize, QKV_SMEM);
    qkv_mma<<<MM / 64, 256, QKV_SMEM>>>(X, bq, bk, bv);

    cudaFuncSetAttribute(attn_kernel, cudaFuncAttributeMaxDynamicSharedMemorySize, ATTN_SMEM);
    attn_kernel<<<dim3(32, BB), 256, ATTN_SMEM>>>(out);
}

// round 4
// speedup vs baseline: 2.3581x; 1.7881x over previous
#include <cuda_runtime.h>
#include <cuda_bf16.h>
#include <cstdint>
#include <math.h>

#define BB 4
#define TT 4096
#define EE 1024
#define DD 64
#define MM (BB*TT)

// ---------------------------------------------------------------------------
// Device scratch (allocation-free rule: device globals)
// ---------------------------------------------------------------------------
// Q,K: [token][64] bf16 hi/lo. V: transposed [b][d][token] bf16 hi/lo.
__device__ __nv_bfloat16 g_qhi[MM*DD];
__device__ __nv_bfloat16 g_qlo[MM*DD];
__device__ __nv_bfloat16 g_khi[MM*DD];
__device__ __nv_bfloat16 g_klo[MM*DD];
__device__ __nv_bfloat16 g_vthi[MM*DD];
__device__ __nv_bfloat16 g_vtlo[MM*DD];

// Pre-split, pre-swizzled bf16 W tiles: [16 k-chunks][192 rows][128 bytes]
#define WCHUNK_BYTES (192*128)
__device__ unsigned char g_whi[16*WCHUNK_BYTES];
__device__ unsigned char g_wlo[16*WCHUNK_BYTES];

// ---------------------------------------------------------------------------
// Helpers
// ---------------------------------------------------------------------------
#define DEVINL __device__ __forceinline__

DEVINL uint32_t smem_u32(const void* p) {
    uint32_t a;
    asm("{ .reg .u64 t; cvta.to.shared.u64 t, %1; cvt.u32.u64 %0, t; }"
        : "=r"(a) : "l"(p));
    return a;
}

#define SWZ128(o) ((o) ^ (((o) >> 3) & 0x70))

#define CP_ASYNC16(dst, src) \
    asm volatile("cp.async.cg.shared.global [%0], [%1], 16;" \
                 :: "r"(dst), "l"(src) : "memory")
#define CP_COMMIT() asm volatile("cp.async.commit_group;" ::: "memory")
#define CP_WAIT0()  asm volatile("cp.async.wait_group 0;"  ::: "memory")

DEVINL uint32_t pack_bf16x2(__nv_bfloat16 a, __nv_bfloat16 b) {
    return (uint32_t)__bfloat16_as_ushort(a) |
           ((uint32_t)__bfloat16_as_ushort(b) << 16);
}
DEVINL void split_bf16(float x, __nv_bfloat16& h, __nv_bfloat16& l) {
    h = __float2bfloat16(x);
    l = __float2bfloat16(x - __bfloat162float(h));
}

DEVINL void ldsm_x4(uint32_t r[4], uint32_t addr) {
    asm volatile("ldmatrix.sync.aligned.m8n8.x4.shared.b16 {%0,%1,%2,%3}, [%4];"
        : "=r"(r[0]), "=r"(r[1]), "=r"(r[2]), "=r"(r[3]) : "r"(addr));
}
DEVINL void ldsm_x2(uint32_t r[2], uint32_t addr) {
    asm volatile("ldmatrix.sync.aligned.m8n8.x2.shared.b16 {%0,%1}, [%2];"
        : "=r"(r[0]), "=r"(r[1]) : "r"(addr));
}
DEVINL void mma16816(float c[4], const uint32_t a[4], const uint32_t b[2]) {
    asm volatile(
        "mma.sync.aligned.m16n8k16.row.col.f32.bf16.bf16.f32 "
        "{%0,%1,%2,%3}, {%4,%5,%6,%7}, {%8,%9}, {%0,%1,%2,%3};"
        : "+f"(c[0]), "+f"(c[1]), "+f"(c[2]), "+f"(c[3])
        : "r"(a[0]), "r"(a[1]), "r"(a[2]), "r"(a[3]), "r"(b[0]), "r"(b[1]));
}

// ---------------------------------------------------------------------------
// W prep (unchanged, verified)
// ---------------------------------------------------------------------------
__global__ void w_prep(const float* __restrict__ Wq,
                       const float* __restrict__ Wk,
                       const float* __restrict__ Wv) {
    const int c = blockIdx.x;
    for (int it = threadIdx.x; it < 1536; it += 256) {
        int n = it % 192;
        int g = it / 192;
        int mat = n >> 6, d = n & 63;
        const float* Wm = (mat == 0) ? Wq : (mat == 1) ? Wk : Wv;
        int kk0 = g * 8;
        uint32_t hi[4], lo[4];
#pragma unroll
        for (int j = 0; j < 4; j++) {
            __nv_bfloat16 h0, l0, h1, l1;
            split_bf16(Wm[(size_t)(c*64 + kk0 + 2*j    ) * 64 + d], h0, l0);
            split_bf16(Wm[(size_t)(c*64 + kk0 + 2*j + 1) * 64 + d], h1, l1);
            hi[j] = pack_bf16x2(h0, h1);
            lo[j] = pack_bf16x2(l0, l1);
        }
        uint32_t sw = SWZ128((uint32_t)n * 128 + (uint32_t)kk0 * 2);
        *(uint4*)(g_whi + (size_t)c * WCHUNK_BYTES + sw) = make_uint4(hi[0], hi[1], hi[2], hi[3]);
        *(uint4*)(g_wlo + (size_t)c * WCHUNK_BYTES + sw) = make_uint4(lo[0], lo[1], lo[2], lo[3]);
    }
}

// ---------------------------------------------------------------------------
// QKV via mma.sync (verified mainloop); epilogue now emits bf16 hi/lo scratch
// ---------------------------------------------------------------------------
#define QB_A_HI 0
#define QB_A_LO 8192
#define QB_B_HI 16384
#define QB_B_LO 40960
#define QB_STRIDE 65536
#define QKV_SMEM (2*QB_STRIDE)

__global__ __launch_bounds__(256, 1) void qkv_mma(
    const float* __restrict__ X,
    const float* __restrict__ bq, const float* __restrict__ bk,
    const float* __restrict__ bv)
{
    extern __shared__ __align__(1024) unsigned char sm[];
    const uint32_t sb = smem_u32(sm);
    const int tid  = threadIdx.x;
    const int warp = tid >> 5;
    const int lane = tid & 31;
    const int m0   = blockIdx.x * 64;
    const int wbase = warp * 24;

    const int rA = (lane & 7) | (((lane >> 3) & 1) << 3);
    const int uA = lane >> 4;
    const int rB = lane & 7;
    const int uB = (lane >> 3) & 1;
    const uint32_t swA = (uint32_t)(rA & 7) << 4;
    const uint32_t swB = (uint32_t)(rB & 7) << 4;

    float acc[4][3][4];
#pragma unroll
    for (int mt = 0; mt < 4; mt++)
#pragma unroll
        for (int nt = 0; nt < 3; nt++)
#pragma unroll
            for (int i = 0; i < 4; i++) acc[mt][nt][i] = 0.f;

    {
#pragma unroll
        for (int j = 0; j < 6; j++) {
            int f = tid + 256 * j;
            CP_ASYNC16(sb + QB_B_HI + f * 16, g_whi + (size_t)f * 16);
            CP_ASYNC16(sb + QB_B_LO + f * 16, g_wlo + (size_t)f * 16);
        }
        CP_COMMIT();
#pragma unroll
        for (int i = 0; i < 4; i++) {
            int f = tid + 256 * i;
            int row = f >> 4, c4 = (f & 15) * 4;
            float4 x = *(const float4*)&X[(size_t)(m0 + row) * EE + c4];
            __nv_bfloat16 h0,l0,h1,l1,h2,l2,h3,l3;
            split_bf16(x.x, h0, l0); split_bf16(x.y, h1, l1);
            split_bf16(x.z, h2, l2); split_bf16(x.w, h3, l3);
            uint32_t off = SWZ128((uint32_t)row * 128 + (uint32_t)c4 * 2);
            *(uint2*)(sm + QB_A_HI + off) = make_uint2(pack_bf16x2(h0,h1), pack_bf16x2(h2,h3));
            *(uint2*)(sm + QB_A_LO + off) = make_uint2(pack_bf16x2(l0,l1), pack_bf16x2(l2,l3));
        }
        CP_WAIT0();
        __syncthreads();
    }

    for (int c = 0; c < 16; c++) {
        const uint32_t bufc = sb + (uint32_t)(c & 1) * QB_STRIDE;
        unsigned char* bn   = sm + ((c + 1) & 1) * QB_STRIDE;
        const uint32_t bufnu = sb + (uint32_t)((c + 1) & 1) * QB_STRIDE;
        const bool hasNext = (c < 15);

        float4 xr[4];
        if (hasNext) {
            const unsigned char* wh = g_whi + (size_t)(c + 1) * WCHUNK_BYTES;
            const unsigned char* wl = g_wlo + (size_t)(c + 1) * WCHUNK_BYTES;
#pragma unroll
            for (int j = 0; j < 6; j++) {
                int f = tid + 256 * j;
                CP_ASYNC16(bufnu + QB_B_HI + f * 16, wh + (size_t)f * 16);
                CP_ASYNC16(bufnu + QB_B_LO + f * 16, wl + (size_t)f * 16);
            }
            CP_COMMIT();
#pragma unroll
            for (int i = 0; i < 4; i++) {
                int f = tid + 256 * i;
                int row = f >> 4, c4 = (f & 15) * 4;
                xr[i] = *(const float4*)&X[(size_t)(m0 + row) * EE + (c + 1) * 64 + c4];
            }
        }

#pragma unroll
        for (int kk = 0; kk < 4; kk++) {
            uint32_t ah[4][4], al[4][4];
#pragma unroll
            for (int mt = 0; mt < 4; mt++) {
                uint32_t ra = bufc + QB_A_HI + (uint32_t)(16*mt + rA) * 128
                            + (((uint32_t)(2*kk + uA) * 16) ^ swA);
                ldsm_x4(ah[mt], ra);
                ldsm_x4(al[mt], ra + (QB_A_LO - QB_A_HI));
            }
            uint32_t bh[3][2], bl[3][2];
#pragma unroll
            for (int nt = 0; nt < 3; nt++) {
                uint32_t rb = bufc + QB_B_HI + (uint32_t)(wbase + 8*nt + rB) * 128
                            + (((uint32_t)(2*kk + uB) * 16) ^ swB);
                ldsm_x2(bh[nt], rb);
                ldsm_x2(bl[nt], rb + (QB_B_LO - QB_B_HI));
            }
#pragma unroll
            for (int mt = 0; mt < 4; mt++)
#pragma unroll
                for (int nt = 0; nt < 3; nt++) {
                    mma16816(acc[mt][nt], ah[mt], bh[nt]);
                    mma16816(acc[mt][nt], ah[mt], bl[nt]);
                    mma16816(acc[mt][nt], al[mt], bh[nt]);
                }
        }

        if (hasNext) {
#pragma unroll
            for (int i = 0; i < 4; i++) {
                int f = tid + 256 * i;
                int row = f >> 4, c4 = (f & 15) * 4;
                __nv_bfloat16 h0,l0,h1,l1,h2,l2,h3,l3;
                split_bf16(xr[i].x, h0, l0); split_bf16(xr[i].y, h1, l1);
                split_bf16(xr[i].z, h2, l2); split_bf16(xr[i].w, h3, l3);
                uint32_t off = SWZ128((uint32_t)row * 128 + (uint32_t)c4 * 2);
                *(uint2*)(bn + QB_A_HI + off) = make_uint2(pack_bf16x2(h0,h1), pack_bf16x2(h2,h3));
                *(uint2*)(bn + QB_A_LO + off) = make_uint2(pack_bf16x2(l0,l1), pack_bf16x2(l2,l3));
            }
            CP_WAIT0();
        }
        __syncthreads();
    }

    // ---- epilogue: bias, bf16 hi/lo split, store to attention scratch ----
    const int gid = lane >> 2, tig = lane & 3;
#pragma unroll
    for (int mt = 0; mt < 4; mt++) {
#pragma unroll
        for (int nt = 0; nt < 3; nt++) {
            const int col0 = wbase + 8 * nt;
            const int mat  = col0 >> 6;
            const int d0   = (col0 & 63) + 2 * tig;
            const float* bp = (mat == 0) ? bq : (mat == 1) ? bk : bv;
            const float b0v = bp[d0], b1v = bp[d0 + 1];
            const int row0 = m0 + 16 * mt + gid;
            float v00 = acc[mt][nt][0] + b0v, v01 = acc[mt][nt][1] + b1v;
            float v10 = acc[mt][nt][2] + b0v, v11 = acc[mt][nt][3] + b1v;
            __nv_bfloat16 h00,l00,h01,l01,h10,l10,h11,l11;
            split_bf16(v00, h00, l00); split_bf16(v01, h01, l01);
            split_bf16(v10, h10, l10); split_bf16(v11, h11, l11);
            if (mat < 2) {
                __nv_bfloat16* dh = mat ? g_khi : g_qhi;
                __nv_bfloat16* dl = mat ? g_klo : g_qlo;
                *(uint32_t*)&dh[(size_t)row0 * DD + d0]       = pack_bf16x2(h00, h01);
                *(uint32_t*)&dl[(size_t)row0 * DD + d0]       = pack_bf16x2(l00, l01);
                *(uint32_t*)&dh[(size_t)(row0 + 8) * DD + d0] = pack_bf16x2(h10, h11);
                *(uint32_t*)&dl[(size_t)(row0 + 8) * DD + d0] = pack_bf16x2(l10, l11);
            } else {
                const int bb = row0 >> 12, t = row0 & 4095;
                size_t r0o = ((size_t)bb * 64 + d0) * TT + t;
                size_t r1o = ((size_t)bb * 64 + d0 + 1) * TT + t;
                g_vthi[r0o]     = h00;  g_vtlo[r0o]     = l00;
                g_vthi[r1o]     = h01;  g_vtlo[r1o]     = l01;
                g_vthi[r0o + 8] = h10;  g_vtlo[r0o + 8] = l10;
                g_vthi[r1o + 8] = h11;  g_vtlo[r1o + 8] = l11;
            }
        }
    }
}

// ---------------------------------------------------------------------------
// Flash attention on mma.sync. CTA = 8 warps, q-tile 128 (warp owns m16),
// kv-tile 64. S and PV both bf16-split (3 MMAs). P stays in registers
// (C-fragment == A-fragment layout). Grid (32, B).
// ---------------------------------------------------------------------------
#define AQ_HI 0
#define AQ_LO 16384
#define ABUF  32768           // per-buffer: KHI 0, KLO 8192, VHI 16384, VLO 24576
#define ABUF_STRIDE 32768
#define ATTN_SMEM (ABUF + 2*ABUF_STRIDE)   // 98304

__global__ __launch_bounds__(256, 1) void attn_mma(float* __restrict__ out)
{
    extern __shared__ __align__(1024) unsigned char sm[];
    const uint32_t sb = smem_u32(sm);
    const int tid  = threadIdx.x;
    const int warp = tid >> 5;
    const int lane = tid & 31;
    const int b    = blockIdx.y;
    const int qt   = blockIdx.x;
    const int qrow0 = qt * 128 + warp * 16;       // within batch
    const int tok0  = b * TT + qt * 128;          // global token of q-tile

    const int gid = lane >> 2, tig = lane & 3;
    const int rA = (lane & 7) | (((lane >> 3) & 1) << 3);
    const int uA = lane >> 4;
    const int rB = lane & 7;
    const int uB = (lane >> 3) & 1;
    const uint32_t swA = (uint32_t)(rA & 7) << 4;
    const uint32_t swB = (uint32_t)(rB) << 4;

    const int jt = 2 * qt + 1;   // kv tiles 0..jt

    // ---- stage Q (hi/lo) + KV tile 0 ----
#pragma unroll
    for (int i = 0; i < 8; i++) {
        int u = tid + 256 * i;                 // 0..2047
        int matq = u >> 10, r = (u >> 3) & 127, cu = u & 7;
        const __nv_bfloat16* src = (matq ? g_qlo : g_qhi)
                                 + (size_t)(tok0 + r) * DD + cu * 8;
        uint32_t dst = sb + matq * 16384 + (uint32_t)r * 128
                     + (((uint32_t)cu * 16) ^ ((uint32_t)(r & 7) << 4));
        CP_ASYNC16(dst, src);
    }
#pragma unroll
    for (int i = 0; i < 8; i++) {
        int u = tid + 256 * i;                 // 0..2047
        int mat = u >> 9, w = u & 511, r = w >> 3, cu = w & 7;
        const __nv_bfloat16* src;
        if (mat == 0)      src = g_khi  + (size_t)(b * TT + r) * DD + cu * 8;
        else if (mat == 1) src = g_klo  + (size_t)(b * TT + r) * DD + cu * 8;
        else if (mat == 2) src = g_vthi + ((size_t)b * 64 + r) * TT + cu * 8;
        else               src = g_vtlo + ((size_t)b * 64 + r) * TT + cu * 8;
        uint32_t dst = sb + ABUF + mat * 8192 + (uint32_t)r * 128
                     + (((uint32_t)cu * 16) ^ ((uint32_t)(r & 7) << 4));
        CP_ASYNC16(dst, src);
    }
    CP_COMMIT();
    CP_WAIT0();
    __syncthreads();

    // ---- hoist Q fragments (invariant over kv loop) ----
    uint32_t qh[4][4], ql[4][4];
#pragma unroll
    for (int kk = 0; kk < 4; kk++) {
        uint32_t ra = sb + AQ_HI + (uint32_t)(warp * 16 + rA) * 128
                    + (((uint32_t)(2*kk + uA) * 16) ^ swA);
        ldsm_x4(qh[kk], ra);
        ldsm_x4(ql[kk], ra + (AQ_LO - AQ_HI));
    }

    float oA[8][4];
#pragma unroll
    for (int nd = 0; nd < 8; nd++)
#pragma unroll
        for (int i = 0; i < 4; i++) oA[nd][i] = 0.f;
    float m0r = -3.0e38f, m1r = -3.0e38f, l0r = 0.f, l1r = 0.f;

    for (int j = 0; j <= jt; j++) {
        CP_WAIT0();
        __syncthreads();
        const uint32_t buf = sb + ABUF + (uint32_t)(j & 1) * ABUF_STRIDE;

        if (j < jt) {   // prefetch next kv tile into other buffer
            const uint32_t bn = sb + ABUF + (uint32_t)((j + 1) & 1) * ABUF_STRIDE;
            const int t0 = (j + 1) * 64;
#pragma unroll
            for (int i = 0; i < 8; i++) {
                int u = tid + 256 * i;
                int mat = u >> 9, w = u & 511, r = w >> 3, cu = w & 7;
                const __nv_bfloat16* src;
                if (mat == 0)      src = g_khi  + (size_t)(b * TT + t0 + r) * DD + cu * 8;
                else if (mat == 1) src = g_klo  + (size_t)(b * TT + t0 + r) * DD + cu * 8;
                else if (mat == 2) src = g_vthi + ((size_t)b * 64 + r) * TT + t0 + cu * 8;
                else               src = g_vtlo + ((size_t)b * 64 + r) * TT + t0 + cu * 8;
                uint32_t dst = bn + mat * 8192 + (uint32_t)r * 128
                             + (((uint32_t)cu * 16) ^ ((uint32_t)(r & 7) << 4));
                CP_ASYNC16(dst, src);
            }
            CP_COMMIT();
        }

        // ---- S = Q . K^T (bf16-split, m16 x n64 x k64 per warp) ----
        float sA[8][4];
#pragma unroll
        for (int nt = 0; nt < 8; nt++)
#pragma unroll
            for (int i = 0; i < 4; i++) sA[nt][i] = 0.f;
#pragma unroll
        for (int kk = 0; kk < 4; kk++) {
#pragma unroll
            for (int nt = 0; nt < 8; nt++) {
                uint32_t rb = buf + (uint32_t)(nt * 8 + rB) * 128
                            + (((uint32_t)(2*kk + uB) * 16) ^ swB);
                uint32_t bh[2], bl[2];
                ldsm_x2(bh, rb);
                ldsm_x2(bl, rb + 8192);
                mma16816(sA[nt], qh[kk], bh);
                mma16816(sA[nt], qh[kk], bl);
                mma16816(sA[nt], ql[kk], bh);
            }
        }

        // ---- scale + causal mask ----
        if (j >= 2 * qt) {
            const int r0 = qrow0 + gid, r1 = r0 + 8;
#pragma unroll
            for (int nt = 0; nt < 8; nt++) {
                int c0 = j * 64 + nt * 8 + 2 * tig;
                sA[nt][0] = (c0     <= r0) ? sA[nt][0] * 0.125f : -1e30f;
                sA[nt][1] = (c0 + 1 <= r0) ? sA[nt][1] * 0.125f : -1e30f;
                sA[nt][2] = (c0     <= r1) ? sA[nt][2] * 0.125f : -1e30f;
                sA[nt][3] = (c0 + 1 <= r1) ? sA[nt][3] * 0.125f : -1e30f;
            }
        } else {
#pragma unroll
            for (int nt = 0; nt < 8; nt++)
#pragma unroll
                for (int i = 0; i < 4; i++) sA[nt][i] *= 0.125f;
        }

        // ---- online softmax (warp-local rows) ----
        float mx0 = sA[0][0], mx1 = sA[0][2];
#pragma unroll
        for (int nt = 0; nt < 8; nt++) {
            mx0 = fmaxf(mx0, fmaxf(sA[nt][0], sA[nt][1]));
            mx1 = fmaxf(mx1, fmaxf(sA[nt][2], sA[nt][3]));
        }
        mx0 = fmaxf(mx0, __shfl_xor_sync(0xffffffffu, mx0, 1));
        mx0 = fmaxf(mx0, __shfl_xor_sync(0xffffffffu, mx0, 2));
        mx1 = fmaxf(mx1, __shfl_xor_sync(0xffffffffu, mx1, 1));
        mx1 = fmaxf(mx1, __shfl_xor_sync(0xffffffffu, mx1, 2));
        float mn0 = fmaxf(m0r, mx0), mn1 = fmaxf(m1r, mx1);
        float al0 = __expf(m0r - mn0), al1 = __expf(m1r - mn1);
        float ps0 = 0.f, ps1 = 0.f;
#pragma unroll
        for (int nt = 0; nt < 8; nt++) {
            sA[nt][0] = __expf(sA[nt][0] - mn0);
            sA[nt][1] = __expf(sA[nt][1] - mn0);
            sA[nt][2] = __expf(sA[nt][2] - mn1);
            sA[nt][3] = __expf(sA[nt][3] - mn1);
            ps0 += sA[nt][0] + sA[nt][1];
            ps1 += sA[nt][2] + sA[nt][3];
        }
        ps0 += __shfl_xor_sync(0xffffffffu, ps0, 1);
        ps0 += __shfl_xor_sync(0xffffffffu, ps0, 2);
        ps1 += __shfl_xor_sync(0xffffffffu, ps1, 1);
        ps1 += __shfl_xor_sync(0xffffffffu, ps1, 2);
        l0r = l0r * al0 + ps0;  m0r = mn0;
        l1r = l1r * al1 + ps1;  m1r = mn1;
#pragma unroll
        for (int nd = 0; nd < 8; nd++) {
            oA[nd][0] *= al0; oA[nd][1] *= al0;
            oA[nd][2] *= al1; oA[nd][3] *= al1;
        }

        // ---- PV: O += P @ V (P in registers; C-frag == A-frag layout) ----
#pragma unroll
        for (int kk = 0; kk < 4; kk++) {
            uint32_t aphi[4], aplo[4];
            {
                __nv_bfloat16 h0,l0,h1,l1;
                split_bf16(sA[2*kk][0], h0, l0);   split_bf16(sA[2*kk][1], h1, l1);
                aphi[0] = pack_bf16x2(h0, h1);     aplo[0] = pack_bf16x2(l0, l1);
                split_bf16(sA[2*kk][2], h0, l0);   split_bf16(sA[2*kk][3], h1, l1);
                aphi[1] = pack_bf16x2(h0, h1);     aplo[1] = pack_bf16x2(l0, l1);
                split_bf16(sA[2*kk+1][0], h0, l0); split_bf16(sA[2*kk+1][1], h1, l1);
                aphi[2] = pack_bf16x2(h0, h1);     aplo[2] = pack_bf16x2(l0, l1);
                split_bf16(sA[2*kk+1][2], h0, l0); split_bf16(sA[2*kk+1][3], h1, l1);
                aphi[3] = pack_bf16x2(h0, h1);     aplo[3] = pack_bf16x2(l0, l1);
            }
#pragma unroll
            for (int nd = 0; nd < 8; nd++) {
                uint32_t rv = buf + 16384 + (uint32_t)(nd * 8 + rB) * 128
                            + (((uint32_t)(2*kk + uB) * 16) ^ swB);
                uint32_t vh[2], vl[2];
                ldsm_x2(vh, rv);
                ldsm_x2(vl, rv + 8192);
                mma16816(oA[nd], aphi, vh);
                mma16816(oA[nd], aphi, vl);
                mma16816(oA[nd], aplo, vh);
            }
        }
    }

    // ---- epilogue ----
    const float inv0 = 1.f / l0r, inv1 = 1.f / l1r;
    const size_t out0 = ((size_t)b * TT + qrow0 + gid) * DD;
    const size_t out1 = ((size_t)b * TT + qrow0 + gid + 8) * DD;
#pragma unroll
    for (int nd = 0; nd < 8; nd++) {
        const int d0 = nd * 8 + 2 * tig;
        *(float2*)&out[out0 + d0] = make_float2(oA[nd][0] * inv0, oA[nd][1] * inv0);
        *(float2*)&out[out1 + d0] = make_float2(oA[nd][2] * inv1, oA[nd][3] * inv1);
    }
}

// ---------------------------------------------------------------------------
extern "C" void kernel_launch(void* const* d_in, const int* in_sizes, int n_in,
                              void* d_out, int out_size)
{
    const float* X  = (const float*)d_in[0];
    const float* Wq = (const float*)d_in[1];
    const float* bq = (const float*)d_in[2];
    const float* Wk = (const float*)d_in[3];
    const float* bk = (const float*)d_in[4];
    const float* Wv = (const float*)d_in[5];
    const float* bv = (const float*)d_in[6];
    float* out = (float*)d_out;

    w_prep<<<16, 256>>>(Wq, Wk, Wv);

    cudaFuncSetAttribute(qkv_mma, cudaFuncAttributeMaxDynamicSharedMemorySize, QKV_SMEM);
    qkv_mma<<<MM / 64, 256, QKV_SMEM>>>(X, bq, bk, bv);

    cudaFuncSetAttribute(attn_mma, cudaFuncAttributeMaxDynamicSharedMemorySize, ATTN_SMEM);
    attn_mma<<<dim3(32, BB), 256, ATTN_SMEM>>>(out);
}

// round 5
// speedup vs baseline: 3.0075x; 1.2754x over previous
#include <cuda_runtime.h>
#include <cuda_bf16.h>
#include <cstdint>
#include <math.h>

#define BB 4
#define TT 4096
#define EE 1024
#define DD 64
#define MM (BB*TT)

// ---------------------------------------------------------------------------
// Device scratch (allocation-free rule: device globals)
// ---------------------------------------------------------------------------
// Q,K: [token][64] bf16 hi/lo. V: transposed [b][d][token] bf16 hi/lo.
__device__ __nv_bfloat16 g_qhi[MM*DD];
__device__ __nv_bfloat16 g_qlo[MM*DD];
__device__ __nv_bfloat16 g_khi[MM*DD];
__device__ __nv_bfloat16 g_klo[MM*DD];
__device__ __nv_bfloat16 g_vthi[MM*DD];
__device__ __nv_bfloat16 g_vtlo[MM*DD];

// Pre-split, pre-swizzled bf16 W tiles: [16 k-chunks][192 rows][128 bytes]
#define WCHUNK_BYTES (192*128)
__device__ unsigned char g_whi[16*WCHUNK_BYTES];
__device__ unsigned char g_wlo[16*WCHUNK_BYTES];

// Pre-split, pre-swizzled bf16 X tiles: [row][16 k-chunks][128 bytes]
__device__ unsigned char g_xhi[(size_t)MM*16*128];
__device__ unsigned char g_xlo[(size_t)MM*16*128];

// ---------------------------------------------------------------------------
// Helpers
// ---------------------------------------------------------------------------
#define DEVINL __device__ __forceinline__

DEVINL uint32_t smem_u32(const void* p) {
    uint32_t a;
    asm("{ .reg .u64 t; cvta.to.shared.u64 t, %1; cvt.u32.u64 %0, t; }"
        : "=r"(a) : "l"(p));
    return a;
}

#define SWZ128(o) ((o) ^ (((o) >> 3) & 0x70))

#define CP_ASYNC16(dst, src) \
    asm volatile("cp.async.cg.shared.global [%0], [%1], 16;" \
                 :: "r"(dst), "l"(src) : "memory")
#define CP_COMMIT() asm volatile("cp.async.commit_group;" ::: "memory")
#define CP_WAIT0()  asm volatile("cp.async.wait_group 0;"  ::: "memory")

#define NB_SYNC(id) asm volatile("bar.sync %0, 128;" :: "r"(id) : "memory")

DEVINL uint32_t pack_bf16x2(__nv_bfloat16 a, __nv_bfloat16 b) {
    return (uint32_t)__bfloat16_as_ushort(a) |
           ((uint32_t)__bfloat16_as_ushort(b) << 16);
}
DEVINL void split_bf16(float x, __nv_bfloat16& h, __nv_bfloat16& l) {
    h = __float2bfloat16(x);
    l = __float2bfloat16(x - __bfloat162float(h));
}

DEVINL void ldsm_x4(uint32_t r[4], uint32_t addr) {
    asm volatile("ldmatrix.sync.aligned.m8n8.x4.shared.b16 {%0,%1,%2,%3}, [%4];"
        : "=r"(r[0]), "=r"(r[1]), "=r"(r[2]), "=r"(r[3]) : "r"(addr));
}
DEVINL void ldsm_x2(uint32_t r[2], uint32_t addr) {
    asm volatile("ldmatrix.sync.aligned.m8n8.x2.shared.b16 {%0,%1}, [%2];"
        : "=r"(r[0]), "=r"(r[1]) : "r"(addr));
}
DEVINL void mma16816(float c[4], const uint32_t a[4], const uint32_t b[2]) {
    asm volatile(
        "mma.sync.aligned.m16n8k16.row.col.f32.bf16.bf16.f32 "
        "{%0,%1,%2,%3}, {%4,%5,%6,%7}, {%8,%9}, {%0,%1,%2,%3};"
        : "+f"(c[0]), "+f"(c[1]), "+f"(c[2]), "+f"(c[3])
        : "r"(a[0]), "r"(a[1]), "r"(a[2]), "r"(a[3]), "r"(b[0]), "r"(b[1]));
}

// ---------------------------------------------------------------------------
// W prep (unchanged, verified)
// ---------------------------------------------------------------------------
__global__ void w_prep(const float* __restrict__ Wq,
                       const float* __restrict__ Wk,
                       const float* __restrict__ Wv) {
    const int c = blockIdx.x;
    for (int it = threadIdx.x; it < 1536; it += 256) {
        int n = it % 192;
        int g = it / 192;
        int mat = n >> 6, d = n & 63;
        const float* Wm = (mat == 0) ? Wq : (mat == 1) ? Wk : Wv;
        int kk0 = g * 8;
        uint32_t hi[4], lo[4];
#pragma unroll
        for (int j = 0; j < 4; j++) {
            __nv_bfloat16 h0, l0, h1, l1;
            split_bf16(Wm[(size_t)(c*64 + kk0 + 2*j    ) * 64 + d], h0, l0);
            split_bf16(Wm[(size_t)(c*64 + kk0 + 2*j + 1) * 64 + d], h1, l1);
            hi[j] = pack_bf16x2(h0, h1);
            lo[j] = pack_bf16x2(l0, l1);
        }
        uint32_t sw = SWZ128((uint32_t)n * 128 + (uint32_t)kk0 * 2);
        *(uint4*)(g_whi + (size_t)c * WCHUNK_BYTES + sw) = make_uint4(hi[0], hi[1], hi[2], hi[3]);
        *(uint4*)(g_wlo + (size_t)c * WCHUNK_BYTES + sw) = make_uint4(lo[0], lo[1], lo[2], lo[3]);
    }
}

// ---------------------------------------------------------------------------
// X prep: fp32 -> bf16 hi/lo, pre-swizzled [row][chunk][128B] layout so qkv
// A-staging is pure linear cp.async.
// ---------------------------------------------------------------------------
__global__ __launch_bounds__(256) void x_prep(const float* __restrict__ X) {
    const int u = blockIdx.x * 256 + threadIdx.x;   // 0 .. MM*128-1
    const int row  = u >> 7;
    const int unit = u & 127;
    const int c    = unit >> 3;
    const int col8 = unit & 7;
    const float4 a = *(const float4*)&X[(size_t)row * EE + c * 64 + col8 * 8];
    const float4 b = *(const float4*)&X[(size_t)row * EE + c * 64 + col8 * 8 + 4];
    __nv_bfloat16 h0,l0,h1,l1,h2,l2,h3,l3,h4,l4,h5,l5,h6,l6,h7,l7;
    split_bf16(a.x, h0, l0); split_bf16(a.y, h1, l1);
    split_bf16(a.z, h2, l2); split_bf16(a.w, h3, l3);
    split_bf16(b.x, h4, l4); split_bf16(b.y, h5, l5);
    split_bf16(b.z, h6, l6); split_bf16(b.w, h7, l7);
    uint4 hh = make_uint4(pack_bf16x2(h0,h1), pack_bf16x2(h2,h3),
                          pack_bf16x2(h4,h5), pack_bf16x2(h6,h7));
    uint4 ll = make_uint4(pack_bf16x2(l0,l1), pack_bf16x2(l2,l3),
                          pack_bf16x2(l4,l5), pack_bf16x2(l6,l7));
    size_t off = (((size_t)row * 16 + c) << 7)
               + ((((uint32_t)col8 * 16) ^ ((uint32_t)(row & 7) << 4)));
    *(uint4*)(g_xhi + off) = hh;
    *(uint4*)(g_xlo + off) = ll;
}

// ---------------------------------------------------------------------------
// QKV via mma.sync; A and W both staged by pure cp.async from pre-split
// global buffers. CTA tile M=64, N=192, k-chunks of 64, double-buffered.
// ---------------------------------------------------------------------------
#define QB_A_HI 0
#define QB_A_LO 8192
#define QB_B_HI 16384
#define QB_B_LO 40960
#define QB_STRIDE 65536
#define QKV_SMEM (2*QB_STRIDE)

__global__ __launch_bounds__(256, 1) void qkv_mma(
    const float* __restrict__ bq, const float* __restrict__ bk,
    const float* __restrict__ bv)
{
    extern __shared__ __align__(1024) unsigned char sm[];
    const uint32_t sb = smem_u32(sm);
    const int tid  = threadIdx.x;
    const int warp = tid >> 5;
    const int lane = tid & 31;
    const int m0   = blockIdx.x * 64;
    const int wbase = warp * 24;

    const int rA = (lane & 7) | (((lane >> 3) & 1) << 3);
    const int uA = lane >> 4;
    const int rB = lane & 7;
    const int uB = (lane >> 3) & 1;
    const uint32_t swA = (uint32_t)(rA & 7) << 4;
    const uint32_t swB = (uint32_t)(rB & 7) << 4;

    float acc[4][3][4];
#pragma unroll
    for (int mt = 0; mt < 4; mt++)
#pragma unroll
        for (int nt = 0; nt < 3; nt++)
#pragma unroll
            for (int i = 0; i < 4; i++) acc[mt][nt][i] = 0.f;

    // ---- stage chunk 0 ----
    {
#pragma unroll
        for (int j = 0; j < 6; j++) {
            int f = tid + 256 * j;
            CP_ASYNC16(sb + QB_B_HI + f * 16, g_whi + (size_t)f * 16);
            CP_ASYNC16(sb + QB_B_LO + f * 16, g_wlo + (size_t)f * 16);
        }
#pragma unroll
        for (int i = 0; i < 4; i++) {
            int u = tid + 256 * i;                    // 0..1023
            int mat = u >> 9, w = u & 511;
            size_t src = (((size_t)(m0 + (w >> 3)) * 16) << 7) + (w & 7) * 16;
            const unsigned char* sp = (mat ? g_xlo : g_xhi) + src;
            CP_ASYNC16(sb + (mat ? QB_A_LO : QB_A_HI) + (uint32_t)w * 16, sp);
        }
        CP_COMMIT();
        CP_WAIT0();
        __syncthreads();
    }

    for (int c = 0; c < 16; c++) {
        const uint32_t bufc = sb + (uint32_t)(c & 1) * QB_STRIDE;
        const uint32_t bufn = sb + (uint32_t)((c + 1) & 1) * QB_STRIDE;
        const bool hasNext = (c < 15);

        if (hasNext) {
            const unsigned char* wh = g_whi + (size_t)(c + 1) * WCHUNK_BYTES;
            const unsigned char* wl = g_wlo + (size_t)(c + 1) * WCHUNK_BYTES;
#pragma unroll
            for (int j = 0; j < 6; j++) {
                int f = tid + 256 * j;
                CP_ASYNC16(bufn + QB_B_HI + f * 16, wh + (size_t)f * 16);
                CP_ASYNC16(bufn + QB_B_LO + f * 16, wl + (size_t)f * 16);
            }
#pragma unroll
            for (int i = 0; i < 4; i++) {
                int u = tid + 256 * i;
                int mat = u >> 9, w = u & 511;
                size_t src = (((size_t)(m0 + (w >> 3)) * 16 + (c + 1)) << 7) + (w & 7) * 16;
                const unsigned char* sp = (mat ? g_xlo : g_xhi) + src;
                CP_ASYNC16(bufn + (mat ? QB_A_LO : QB_A_HI) + (uint32_t)w * 16, sp);
            }
            CP_COMMIT();
        }

        // ---- compute on bufc: 4 k16 steps ----
#pragma unroll
        for (int kk = 0; kk < 4; kk++) {
            uint32_t ah[4][4], al[4][4];
#pragma unroll
            for (int mt = 0; mt < 4; mt++) {
                uint32_t ra = bufc + QB_A_HI + (uint32_t)(16*mt + rA) * 128
                            + (((uint32_t)(2*kk + uA) * 16) ^ swA);
                ldsm_x4(ah[mt], ra);
                ldsm_x4(al[mt], ra + (QB_A_LO - QB_A_HI));
            }
            uint32_t bh[3][2], bl[3][2];
#pragma unroll
            for (int nt = 0; nt < 3; nt++) {
                uint32_t rb = bufc + QB_B_HI + (uint32_t)(wbase + 8*nt + rB) * 128
                            + (((uint32_t)(2*kk + uB) * 16) ^ swB);
                ldsm_x2(bh[nt], rb);
                ldsm_x2(bl[nt], rb + (QB_B_LO - QB_B_HI));
            }
#pragma unroll
            for (int mt = 0; mt < 4; mt++)
#pragma unroll
                for (int nt = 0; nt < 3; nt++) {
                    mma16816(acc[mt][nt], ah[mt], bh[nt]);
                    mma16816(acc[mt][nt], ah[mt], bl[nt]);
                    mma16816(acc[mt][nt], al[mt], bh[nt]);
                }
        }

        CP_WAIT0();
        __syncthreads();
    }

    // ---- epilogue: bias, bf16 hi/lo split, store to attention scratch ----
    const int gid = lane >> 2, tig = lane & 3;
#pragma unroll
    for (int mt = 0; mt < 4; mt++) {
#pragma unroll
        for (int nt = 0; nt < 3; nt++) {
            const int col0 = wbase + 8 * nt;
            const int mat  = col0 >> 6;
            const int d0   = (col0 & 63) + 2 * tig;
            const float* bp = (mat == 0) ? bq : (mat == 1) ? bk : bv;
            const float b0v = bp[d0], b1v = bp[d0 + 1];
            const int row0 = m0 + 16 * mt + gid;
            float v00 = acc[mt][nt][0] + b0v, v01 = acc[mt][nt][1] + b1v;
            float v10 = acc[mt][nt][2] + b0v, v11 = acc[mt][nt][3] + b1v;
            __nv_bfloat16 h00,l00,h01,l01,h10,l10,h11,l11;
            split_bf16(v00, h00, l00); split_bf16(v01, h01, l01);
            split_bf16(v10, h10, l10); split_bf16(v11, h11, l11);
            if (mat < 2) {
                __nv_bfloat16* dh = mat ? g_khi : g_qhi;
                __nv_bfloat16* dl = mat ? g_klo : g_qlo;
                *(uint32_t*)&dh[(size_t)row0 * DD + d0]       = pack_bf16x2(h00, h01);
                *(uint32_t*)&dl[(size_t)row0 * DD + d0]       = pack_bf16x2(l00, l01);
                *(uint32_t*)&dh[(size_t)(row0 + 8) * DD + d0] = pack_bf16x2(h10, h11);
                *(uint32_t*)&dl[(size_t)(row0 + 8) * DD + d0] = pack_bf16x2(l10, l11);
            } else {
                const int bb = row0 >> 12, t = row0 & 4095;
                size_t r0o = ((size_t)bb * 64 + d0) * TT + t;
                size_t r1o = ((size_t)bb * 64 + d0 + 1) * TT + t;
                g_vthi[r0o]     = h00;  g_vtlo[r0o]     = l00;
                g_vthi[r1o]     = h01;  g_vtlo[r1o]     = l01;
                g_vthi[r0o + 8] = h10;  g_vtlo[r0o + 8] = l10;
                g_vthi[r1o + 8] = h11;  g_vtlo[r1o + 8] = l11;
            }
        }
    }
}

// ---------------------------------------------------------------------------
// Flash attention on mma.sync. 8 warps; warps 0-3 process q-tile qp, warps
// 4-7 process q-tile 63-qp -> every CTA does exactly 65 kv-tiles of work.
// Halves are fully independent (own smem half, named barriers). Grid (32, B).
// Per-half smem: Q hi/lo 16KB + 2 kv buffers of 32KB = 80KB.
// ---------------------------------------------------------------------------
#define AH_STRIDE 81920
#define ATTN_SMEM (2*AH_STRIDE)   // 163840

DEVINL void stage_kv(uint32_t dstbase, int htid, int b, int t0) {
#pragma unroll
    for (int i = 0; i < 16; i++) {
        int u = htid + 128 * i;                // 0..2047
        int mat = u >> 9, w = u & 511, r = w >> 3, cu = w & 7;
        const __nv_bfloat16* src;
        if (mat == 0)      src = g_khi  + (size_t)(b * TT + t0 + r) * DD + cu * 8;
        else if (mat == 1) src = g_klo  + (size_t)(b * TT + t0 + r) * DD + cu * 8;
        else if (mat == 2) src = g_vthi + ((size_t)b * DD + r) * TT + t0 + cu * 8;
        else               src = g_vtlo + ((size_t)b * DD + r) * TT + t0 + cu * 8;
        uint32_t dst = dstbase + mat * 8192 + (uint32_t)r * 128
                     + (((uint32_t)cu * 16) ^ ((uint32_t)(r & 7) << 4));
        CP_ASYNC16(dst, src);
    }
}

__global__ __launch_bounds__(256, 1) void attn_mma(float* __restrict__ out)
{
    extern __shared__ __align__(1024) unsigned char sm[];
    const uint32_t sb = smem_u32(sm);
    const int tid  = threadIdx.x;
    const int warp = tid >> 5;
    const int lane = tid & 31;
    const int half = warp >> 2;            // 0 or 1
    const int wh   = warp & 3;
    const int htid = tid & 127;
    const int b    = blockIdx.y;
    const int qp   = blockIdx.x;
    const int qt   = half ? (63 - qp) : qp;        // q-tile (64 rows)
    const uint32_t hb = sb + (uint32_t)half * AH_STRIDE;
    const int tok0 = b * TT + qt * 64;
    const int nbid = half + 1;

    const int gid = lane >> 2, tig = lane & 3;
    const int rA = (lane & 7) | (((lane >> 3) & 1) << 3);
    const int uA = lane >> 4;
    const int rB = lane & 7;
    const int uB = (lane >> 3) & 1;
    const uint32_t swA = (uint32_t)(rA & 7) << 4;
    const uint32_t swB = (uint32_t)(rB) << 4;

    // ---- stage Q (hi/lo, 8 cp) + KV tile 0 (16 cp) ----
#pragma unroll
    for (int i = 0; i < 8; i++) {
        int u = htid + 128 * i;                // 0..1023
        int matq = u >> 9, r = (u >> 3) & 63, cu = u & 7;
        const __nv_bfloat16* src = (matq ? g_qlo : g_qhi)
                                 + (size_t)(tok0 + r) * DD + cu * 8;
        uint32_t dst = hb + matq * 8192 + (uint32_t)r * 128
                     + (((uint32_t)cu * 16) ^ ((uint32_t)(r & 7) << 4));
        CP_ASYNC16(dst, src);
    }
    stage_kv(hb + 16384, htid, b, 0);
    CP_COMMIT();
    CP_WAIT0();
    NB_SYNC(nbid);

    // ---- hoist Q fragments ----
    uint32_t qh[4][4], ql[4][4];
#pragma unroll
    for (int kk = 0; kk < 4; kk++) {
        uint32_t ra = hb + (uint32_t)(wh * 16 + rA) * 128
                    + (((uint32_t)(2*kk + uA) * 16) ^ swA);
        ldsm_x4(qh[kk], ra);
        ldsm_x4(ql[kk], ra + 8192);
    }

    float oA[8][4];
#pragma unroll
    for (int nd = 0; nd < 8; nd++)
#pragma unroll
        for (int i = 0; i < 4; i++) oA[nd][i] = 0.f;
    float m0r = -3.0e38f, m1r = -3.0e38f, l0r = 0.f, l1r = 0.f;

    for (int j = 0; j <= qt; j++) {
        if (j) { CP_WAIT0(); NB_SYNC(nbid); }
        const uint32_t buf = hb + 16384 + (uint32_t)(j & 1) * 32768;

        if (j < qt) {
            stage_kv(hb + 16384 + (uint32_t)((j + 1) & 1) * 32768, htid, b, (j + 1) * 64);
            CP_COMMIT();
        }

        // ---- S = Q . K^T ----
        float sA[8][4];
#pragma unroll
        for (int nt = 0; nt < 8; nt++)
#pragma unroll
            for (int i = 0; i < 4; i++) sA[nt][i] = 0.f;
#pragma unroll
        for (int kk = 0; kk < 4; kk++) {
#pragma unroll
            for (int nt = 0; nt < 8; nt++) {
                uint32_t rb = buf + (uint32_t)(nt * 8 + rB) * 128
                            + (((uint32_t)(2*kk + uB) * 16) ^ swB);
                uint32_t bh[2], bl[2];
                ldsm_x2(bh, rb);
                ldsm_x2(bl, rb + 8192);
                mma16816(sA[nt], qh[kk], bh);
                mma16816(sA[nt], qh[kk], bl);
                mma16816(sA[nt], ql[kk], bh);
            }
        }

        // ---- scale + causal mask (diagonal tile only) ----
        if (j == qt) {
            const int r0 = qt * 64 + wh * 16 + gid, r1 = r0 + 8;
#pragma unroll
            for (int nt = 0; nt < 8; nt++) {
                int c0 = j * 64 + nt * 8 + 2 * tig;
                sA[nt][0] = (c0     <= r0) ? sA[nt][0] * 0.125f : -1e30f;
                sA[nt][1] = (c0 + 1 <= r0) ? sA[nt][1] * 0.125f : -1e30f;
                sA[nt][2] = (c0     <= r1) ? sA[nt][2] * 0.125f : -1e30f;
                sA[nt][3] = (c0 + 1 <= r1) ? sA[nt][3] * 0.125f : -1e30f;
            }
        } else {
#pragma unroll
            for (int nt = 0; nt < 8; nt++)
#pragma unroll
                for (int i = 0; i < 4; i++) sA[nt][i] *= 0.125f;
        }

        // ---- online softmax (warp-local rows) ----
        float mx0 = sA[0][0], mx1 = sA[0][2];
#pragma unroll
        for (int nt = 0; nt < 8; nt++) {
            mx0 = fmaxf(mx0, fmaxf(sA[nt][0], sA[nt][1]));
            mx1 = fmaxf(mx1, fmaxf(sA[nt][2], sA[nt][3]));
        }
        mx0 = fmaxf(mx0, __shfl_xor_sync(0xffffffffu, mx0, 1));
        mx0 = fmaxf(mx0, __shfl_xor_sync(0xffffffffu, mx0, 2));
        mx1 = fmaxf(mx1, __shfl_xor_sync(0xffffffffu, mx1, 1));
        mx1 = fmaxf(mx1, __shfl_xor_sync(0xffffffffu, mx1, 2));
        float mn0 = fmaxf(m0r, mx0), mn1 = fmaxf(m1r, mx1);
        float al0 = __expf(m0r - mn0), al1 = __expf(m1r - mn1);
        float ps0 = 0.f, ps1 = 0.f;
#pragma unroll
        for (int nt = 0; nt < 8; nt++) {
            sA[nt][0] = __expf(sA[nt][0] - mn0);
            sA[nt][1] = __expf(sA[nt][1] - mn0);
            sA[nt][2] = __expf(sA[nt][2] - mn1);
            sA[nt][3] = __expf(sA[nt][3] - mn1);
            ps0 += sA[nt][0] + sA[nt][1];
            ps1 += sA[nt][2] + sA[nt][3];
        }
        ps0 += __shfl_xor_sync(0xffffffffu, ps0, 1);
        ps0 += __shfl_xor_sync(0xffffffffu, ps0, 2);
        ps1 += __shfl_xor_sync(0xffffffffu, ps1, 1);
        ps1 += __shfl_xor_sync(0xffffffffu, ps1, 2);
        l0r = l0r * al0 + ps0;  m0r = mn0;
        l1r = l1r * al1 + ps1;  m1r = mn1;
#pragma unroll
        for (int nd = 0; nd < 8; nd++) {
            oA[nd][0] *= al0; oA[nd][1] *= al0;
            oA[nd][2] *= al1; oA[nd][3] *= al1;
        }

        // ---- PV: O += P @ V (P in registers) ----
#pragma unroll
        for (int kk = 0; kk < 4; kk++) {
            uint32_t aphi[4], aplo[4];
            {
                __nv_bfloat16 h0,l0,h1,l1;
                split_bf16(sA[2*kk][0], h0, l0);   split_bf16(sA[2*kk][1], h1, l1);
                aphi[0] = pack_bf16x2(h0, h1);     aplo[0] = pack_bf16x2(l0, l1);
                split_bf16(sA[2*kk][2], h0, l0);   split_bf16(sA[2*kk][3], h1, l1);
                aphi[1] = pack_bf16x2(h0, h1);     aplo[1] = pack_bf16x2(l0, l1);
                split_bf16(sA[2*kk+1][0], h0, l0); split_bf16(sA[2*kk+1][1], h1, l1);
                aphi[2] = pack_bf16x2(h0, h1);     aplo[2] = pack_bf16x2(l0, l1);
                split_bf16(sA[2*kk+1][2], h0, l0); split_bf16(sA[2*kk+1][3], h1, l1);
                aphi[3] = pack_bf16x2(h0, h1);     aplo[3] = pack_bf16x2(l0, l1);
            }
#pragma unroll
            for (int nd = 0; nd < 8; nd++) {
                uint32_t rv = buf + 16384 + (uint32_t)(nd * 8 + rB) * 128
                            + (((uint32_t)(2*kk + uB) * 16) ^ swB);
                uint32_t vh[2], vl[2];
                ldsm_x2(vh, rv);
                ldsm_x2(vl, rv + 8192);
                mma16816(oA[nd], aphi, vh);
                mma16816(oA[nd], aphi, vl);
                mma16816(oA[nd], aplo, vh);
            }
        }
    }

    // ---- epilogue ----
    const float inv0 = 1.f / l0r, inv1 = 1.f / l1r;
    const size_t out0 = ((size_t)b * TT + qt * 64 + wh * 16 + gid) * DD;
    const size_t out1 = out0 + 8 * DD;
#pragma unroll
    for (int nd = 0; nd < 8; nd++) {
        const int d0 = nd * 8 + 2 * tig;
        *(float2*)&out[out0 + d0] = make_float2(oA[nd][0] * inv0, oA[nd][1] * inv0);
        *(float2*)&out[out1 + d0] = make_float2(oA[nd][2] * inv1, oA[nd][3] * inv1);
    }
}

// ---------------------------------------------------------------------------
extern "C" void kernel_launch(void* const* d_in, const int* in_sizes, int n_in,
                              void* d_out, int out_size)
{
    const float* X  = (const float*)d_in[0];
    const float* Wq = (const float*)d_in[1];
    const float* bq = (const float*)d_in[2];
    const float* Wk = (const float*)d_in[3];
    const float* bk = (const float*)d_in[4];
    const float* Wv = (const float*)d_in[5];
    const float* bv = (const float*)d_in[6];
    float* out = (float*)d_out;

    x_prep<<<MM * 128 / 256, 256>>>(X);
    w_prep<<<16, 256>>>(Wq, Wk, Wv);

    cudaFuncSetAttribute(qkv_mma, cudaFuncAttributeMaxDynamicSharedMemorySize, QKV_SMEM);
    qkv_mma<<<MM / 64, 256, QKV_SMEM>>>(bq, bk, bv);

    cudaFuncSetAttribute(attn_mma, cudaFuncAttributeMaxDynamicSharedMemorySize, ATTN_SMEM);
    attn_mma<<<dim3(32, BB), 256, ATTN_SMEM>>>(out);
}

// round 6
// speedup vs baseline: 3.0374x; 1.0099x over previous
#include <cuda_runtime.h>
#include <cuda_bf16.h>
#include <cstdint>
#include <math.h>

#define BB 4
#define TT 4096
#define EE 1024
#define DD 64
#define MM (BB*TT)

// ---------------------------------------------------------------------------
// Device scratch (allocation-free rule: device globals)
// ---------------------------------------------------------------------------
__device__ __nv_bfloat16 g_qhi[MM*DD];
__device__ __nv_bfloat16 g_qlo[MM*DD];
__device__ __nv_bfloat16 g_khi[MM*DD];
__device__ __nv_bfloat16 g_klo[MM*DD];
__device__ __nv_bfloat16 g_vthi[MM*DD];
__device__ __nv_bfloat16 g_vtlo[MM*DD];

#define WCHUNK_BYTES (192*128)
__device__ unsigned char g_whi[16*WCHUNK_BYTES];
__device__ unsigned char g_wlo[16*WCHUNK_BYTES];

// Pre-split, pre-swizzled bf16 X tiles: [row][16 k-chunks][128 bytes]
__device__ unsigned char g_xhi[(size_t)MM*16*128];
__device__ unsigned char g_xlo[(size_t)MM*16*128];

// ---------------------------------------------------------------------------
// Helpers
// ---------------------------------------------------------------------------
#define DEVINL __device__ __forceinline__

DEVINL uint32_t smem_u32(const void* p) {
    uint32_t a;
    asm("{ .reg .u64 t; cvta.to.shared.u64 t, %1; cvt.u32.u64 %0, t; }"
        : "=r"(a) : "l"(p));
    return a;
}

#define SWZ128(o) ((o) ^ (((o) >> 3) & 0x70))

#define CP_ASYNC16(dst, src) \
    asm volatile("cp.async.cg.shared.global [%0], [%1], 16;" \
                 :: "r"(dst), "l"(src) : "memory")
#define CP_COMMIT() asm volatile("cp.async.commit_group;" ::: "memory")
#define CP_WAIT0()  asm volatile("cp.async.wait_group 0;"  ::: "memory")

#define NB_SYNC(id) asm volatile("bar.sync %0, 128;" :: "r"(id) : "memory")

DEVINL uint32_t pack_bf16x2(__nv_bfloat16 a, __nv_bfloat16 b) {
    return (uint32_t)__bfloat16_as_ushort(a) |
           ((uint32_t)__bfloat16_as_ushort(b) << 16);
}
DEVINL void split_bf16(float x, __nv_bfloat16& h, __nv_bfloat16& l) {
    h = __float2bfloat16(x);
    l = __float2bfloat16(x - __bfloat162float(h));
}

DEVINL void ldsm_x4(uint32_t r[4], uint32_t addr) {
    asm volatile("ldmatrix.sync.aligned.m8n8.x4.shared.b16 {%0,%1,%2,%3}, [%4];"
        : "=r"(r[0]), "=r"(r[1]), "=r"(r[2]), "=r"(r[3]) : "r"(addr));
}
DEVINL void ldsm_x2(uint32_t r[2], uint32_t addr) {
    asm volatile("ldmatrix.sync.aligned.m8n8.x2.shared.b16 {%0,%1}, [%2];"
        : "=r"(r[0]), "=r"(r[1]) : "r"(addr));
}
DEVINL void mma16816(float c[4], const uint32_t a[4], const uint32_t b[2]) {
    asm volatile(
        "mma.sync.aligned.m16n8k16.row.col.f32.bf16.bf16.f32 "
        "{%0,%1,%2,%3}, {%4,%5,%6,%7}, {%8,%9}, {%0,%1,%2,%3};"
        : "+f"(c[0]), "+f"(c[1]), "+f"(c[2]), "+f"(c[3])
        : "r"(a[0]), "r"(a[1]), "r"(a[2]), "r"(a[3]), "r"(b[0]), "r"(b[1]));
}

// ---------------------------------------------------------------------------
// W prep (verified)
// ---------------------------------------------------------------------------
__global__ void w_prep(const float* __restrict__ Wq,
                       const float* __restrict__ Wk,
                       const float* __restrict__ Wv) {
    const int c = blockIdx.x;
    for (int it = threadIdx.x; it < 1536; it += 256) {
        int n = it % 192;
        int g = it / 192;
        int mat = n >> 6, d = n & 63;
        const float* Wm = (mat == 0) ? Wq : (mat == 1) ? Wk : Wv;
        int kk0 = g * 8;
        uint32_t hi[4], lo[4];
#pragma unroll
        for (int j = 0; j < 4; j++) {
            __nv_bfloat16 h0, l0, h1, l1;
            split_bf16(Wm[(size_t)(c*64 + kk0 + 2*j    ) * 64 + d], h0, l0);
            split_bf16(Wm[(size_t)(c*64 + kk0 + 2*j + 1) * 64 + d], h1, l1);
            hi[j] = pack_bf16x2(h0, h1);
            lo[j] = pack_bf16x2(l0, l1);
        }
        uint32_t sw = SWZ128((uint32_t)n * 128 + (uint32_t)kk0 * 2);
        *(uint4*)(g_whi + (size_t)c * WCHUNK_BYTES + sw) = make_uint4(hi[0], hi[1], hi[2], hi[3]);
        *(uint4*)(g_wlo + (size_t)c * WCHUNK_BYTES + sw) = make_uint4(lo[0], lo[1], lo[2], lo[3]);
    }
}

// ---------------------------------------------------------------------------
// X prep (verified)
// ---------------------------------------------------------------------------
__global__ __launch_bounds__(256) void x_prep(const float* __restrict__ X) {
    const int u = blockIdx.x * 256 + threadIdx.x;
    const int row  = u >> 7;
    const int unit = u & 127;
    const int c    = unit >> 3;
    const int col8 = unit & 7;
    const float4 a = *(const float4*)&X[(size_t)row * EE + c * 64 + col8 * 8];
    const float4 b = *(const float4*)&X[(size_t)row * EE + c * 64 + col8 * 8 + 4];
    __nv_bfloat16 h0,l0,h1,l1,h2,l2,h3,l3,h4,l4,h5,l5,h6,l6,h7,l7;
    split_bf16(a.x, h0, l0); split_bf16(a.y, h1, l1);
    split_bf16(a.z, h2, l2); split_bf16(a.w, h3, l3);
    split_bf16(b.x, h4, l4); split_bf16(b.y, h5, l5);
    split_bf16(b.z, h6, l6); split_bf16(b.w, h7, l7);
    uint4 hh = make_uint4(pack_bf16x2(h0,h1), pack_bf16x2(h2,h3),
                          pack_bf16x2(h4,h5), pack_bf16x2(h6,h7));
    uint4 ll = make_uint4(pack_bf16x2(l0,l1), pack_bf16x2(l2,l3),
                          pack_bf16x2(l4,l5), pack_bf16x2(l6,l7));
    size_t off = (((size_t)row * 16 + c) << 7)
               + ((((uint32_t)col8 * 16) ^ ((uint32_t)(row & 7) << 4)));
    *(uint4*)(g_xhi + off) = hh;
    *(uint4*)(g_xlo + off) = ll;
}

// ---------------------------------------------------------------------------
// QKV via mma.sync. MMAs issued term-by-term: 12 independent accumulators
// between dependent revisits (was 1 -> latency-bound).
// ---------------------------------------------------------------------------
#define QB_A_HI 0
#define QB_A_LO 8192
#define QB_B_HI 16384
#define QB_B_LO 40960
#define QB_STRIDE 65536
#define QKV_SMEM (2*QB_STRIDE)

__global__ __launch_bounds__(256, 1) void qkv_mma(
    const float* __restrict__ bq, const float* __restrict__ bk,
    const float* __restrict__ bv)
{
    extern __shared__ __align__(1024) unsigned char sm[];
    const uint32_t sb = smem_u32(sm);
    const int tid  = threadIdx.x;
    const int warp = tid >> 5;
    const int lane = tid & 31;
    const int m0   = blockIdx.x * 64;
    const int wbase = warp * 24;

    const int rA = (lane & 7) | (((lane >> 3) & 1) << 3);
    const int uA = lane >> 4;
    const int rB = lane & 7;
    const int uB = (lane >> 3) & 1;
    const uint32_t swA = (uint32_t)(rA & 7) << 4;
    const uint32_t swB = (uint32_t)(rB & 7) << 4;

    float acc[4][3][4];
#pragma unroll
    for (int mt = 0; mt < 4; mt++)
#pragma unroll
        for (int nt = 0; nt < 3; nt++)
#pragma unroll
            for (int i = 0; i < 4; i++) acc[mt][nt][i] = 0.f;

    {
#pragma unroll
        for (int j = 0; j < 6; j++) {
            int f = tid + 256 * j;
            CP_ASYNC16(sb + QB_B_HI + f * 16, g_whi + (size_t)f * 16);
            CP_ASYNC16(sb + QB_B_LO + f * 16, g_wlo + (size_t)f * 16);
        }
#pragma unroll
        for (int i = 0; i < 4; i++) {
            int u = tid + 256 * i;
            int mat = u >> 9, w = u & 511;
            size_t src = (((size_t)(m0 + (w >> 3)) * 16) << 7) + (w & 7) * 16;
            const unsigned char* sp = (mat ? g_xlo : g_xhi) + src;
            CP_ASYNC16(sb + (mat ? QB_A_LO : QB_A_HI) + (uint32_t)w * 16, sp);
        }
        CP_COMMIT();
        CP_WAIT0();
        __syncthreads();
    }

    for (int c = 0; c < 16; c++) {
        const uint32_t bufc = sb + (uint32_t)(c & 1) * QB_STRIDE;
        const uint32_t bufn = sb + (uint32_t)((c + 1) & 1) * QB_STRIDE;
        const bool hasNext = (c < 15);

        if (hasNext) {
            const unsigned char* wh = g_whi + (size_t)(c + 1) * WCHUNK_BYTES;
            const unsigned char* wl = g_wlo + (size_t)(c + 1) * WCHUNK_BYTES;
#pragma unroll
            for (int j = 0; j < 6; j++) {
                int f = tid + 256 * j;
                CP_ASYNC16(bufn + QB_B_HI + f * 16, wh + (size_t)f * 16);
                CP_ASYNC16(bufn + QB_B_LO + f * 16, wl + (size_t)f * 16);
            }
#pragma unroll
            for (int i = 0; i < 4; i++) {
                int u = tid + 256 * i;
                int mat = u >> 9, w = u & 511;
                size_t src = (((size_t)(m0 + (w >> 3)) * 16 + (c + 1)) << 7) + (w & 7) * 16;
                const unsigned char* sp = (mat ? g_xlo : g_xhi) + src;
                CP_ASYNC16(bufn + (mat ? QB_A_LO : QB_A_HI) + (uint32_t)w * 16, sp);
            }
            CP_COMMIT();
        }

#pragma unroll
        for (int kk = 0; kk < 4; kk++) {
            uint32_t ah[4][4], al[4][4];
#pragma unroll
            for (int mt = 0; mt < 4; mt++) {
                uint32_t ra = bufc + QB_A_HI + (uint32_t)(16*mt + rA) * 128
                            + (((uint32_t)(2*kk + uA) * 16) ^ swA);
                ldsm_x4(ah[mt], ra);
                ldsm_x4(al[mt], ra + (QB_A_LO - QB_A_HI));
            }
            uint32_t bh[3][2], bl[3][2];
#pragma unroll
            for (int nt = 0; nt < 3; nt++) {
                uint32_t rb = bufc + QB_B_HI + (uint32_t)(wbase + 8*nt + rB) * 128
                            + (((uint32_t)(2*kk + uB) * 16) ^ swB);
                ldsm_x2(bh[nt], rb);
                ldsm_x2(bl[nt], rb + (QB_B_LO - QB_B_HI));
            }
            // term-major issue: 12 independent accumulators per pass
#pragma unroll
            for (int mt = 0; mt < 4; mt++)
#pragma unroll
                for (int nt = 0; nt < 3; nt++)
                    mma16816(acc[mt][nt], ah[mt], bh[nt]);
#pragma unroll
            for (int mt = 0; mt < 4; mt++)
#pragma unroll
                for (int nt = 0; nt < 3; nt++)
                    mma16816(acc[mt][nt], ah[mt], bl[nt]);
#pragma unroll
            for (int mt = 0; mt < 4; mt++)
#pragma unroll
                for (int nt = 0; nt < 3; nt++)
                    mma16816(acc[mt][nt], al[mt], bh[nt]);
        }

        CP_WAIT0();
        __syncthreads();
    }

    const int gid = lane >> 2, tig = lane & 3;
#pragma unroll
    for (int mt = 0; mt < 4; mt++) {
#pragma unroll
        for (int nt = 0; nt < 3; nt++) {
            const int col0 = wbase + 8 * nt;
            const int mat  = col0 >> 6;
            const int d0   = (col0 & 63) + 2 * tig;
            const float* bp = (mat == 0) ? bq : (mat == 1) ? bk : bv;
            const float b0v = bp[d0], b1v = bp[d0 + 1];
            const int row0 = m0 + 16 * mt + gid;
            float v00 = acc[mt][nt][0] + b0v, v01 = acc[mt][nt][1] + b1v;
            float v10 = acc[mt][nt][2] + b0v, v11 = acc[mt][nt][3] + b1v;
            __nv_bfloat16 h00,l00,h01,l01,h10,l10,h11,l11;
            split_bf16(v00, h00, l00); split_bf16(v01, h01, l01);
            split_bf16(v10, h10, l10); split_bf16(v11, h11, l11);
            if (mat < 2) {
                __nv_bfloat16* dh = mat ? g_khi : g_qhi;
                __nv_bfloat16* dl = mat ? g_klo : g_qlo;
                *(uint32_t*)&dh[(size_t)row0 * DD + d0]       = pack_bf16x2(h00, h01);
                *(uint32_t*)&dl[(size_t)row0 * DD + d0]       = pack_bf16x2(l00, l01);
                *(uint32_t*)&dh[(size_t)(row0 + 8) * DD + d0] = pack_bf16x2(h10, h11);
                *(uint32_t*)&dl[(size_t)(row0 + 8) * DD + d0] = pack_bf16x2(l10, l11);
            } else {
                const int bb = row0 >> 12, t = row0 & 4095;
                size_t r0o = ((size_t)bb * 64 + d0) * TT + t;
                size_t r1o = ((size_t)bb * 64 + d0 + 1) * TT + t;
                g_vthi[r0o]     = h00;  g_vtlo[r0o]     = l00;
                g_vthi[r1o]     = h01;  g_vtlo[r1o]     = l01;
                g_vthi[r0o + 8] = h10;  g_vtlo[r0o + 8] = l10;
                g_vthi[r1o + 8] = h11;  g_vtlo[r1o + 8] = l11;
            }
        }
    }
}

// ---------------------------------------------------------------------------
// Flash attention on mma.sync; paired q-tiles (qp, 63-qp) per CTA; MMAs
// issued term-by-term (8 independent accumulators between revisits).
// ---------------------------------------------------------------------------
#define AH_STRIDE 81920
#define ATTN_SMEM (2*AH_STRIDE)

DEVINL void stage_kv(uint32_t dstbase, int htid, int b, int t0) {
#pragma unroll
    for (int i = 0; i < 16; i++) {
        int u = htid + 128 * i;
        int mat = u >> 9, w = u & 511, r = w >> 3, cu = w & 7;
        const __nv_bfloat16* src;
        if (mat == 0)      src = g_khi  + (size_t)(b * TT + t0 + r) * DD + cu * 8;
        else if (mat == 1) src = g_klo  + (size_t)(b * TT + t0 + r) * DD + cu * 8;
        else if (mat == 2) src = g_vthi + ((size_t)b * DD + r) * TT + t0 + cu * 8;
        else               src = g_vtlo + ((size_t)b * DD + r) * TT + t0 + cu * 8;
        uint32_t dst = dstbase + mat * 8192 + (uint32_t)r * 128
                     + (((uint32_t)cu * 16) ^ ((uint32_t)(r & 7) << 4));
        CP_ASYNC16(dst, src);
    }
}

__global__ __launch_bounds__(256, 1) void attn_mma(float* __restrict__ out)
{
    extern __shared__ __align__(1024) unsigned char sm[];
    const uint32_t sb = smem_u32(sm);
    const int tid  = threadIdx.x;
    const int warp = tid >> 5;
    const int lane = tid & 31;
    const int half = warp >> 2;
    const int wh   = warp & 3;
    const int htid = tid & 127;
    const int b    = blockIdx.y;
    const int qp   = blockIdx.x;
    const int qt   = half ? (63 - qp) : qp;
    const uint32_t hb = sb + (uint32_t)half * AH_STRIDE;
    const int tok0 = b * TT + qt * 64;
    const int nbid = half + 1;

    const int gid = lane >> 2, tig = lane & 3;
    const int rA = (lane & 7) | (((lane >> 3) & 1) << 3);
    const int uA = lane >> 4;
    const int rB = lane & 7;
    const int uB = (lane >> 3) & 1;
    const uint32_t swA = (uint32_t)(rA & 7) << 4;
    const uint32_t swB = (uint32_t)(rB) << 4;

#pragma unroll
    for (int i = 0; i < 8; i++) {
        int u = htid + 128 * i;
        int matq = u >> 9, r = (u >> 3) & 63, cu = u & 7;
        const __nv_bfloat16* src = (matq ? g_qlo : g_qhi)
                                 + (size_t)(tok0 + r) * DD + cu * 8;
        uint32_t dst = hb + matq * 8192 + (uint32_t)r * 128
                     + (((uint32_t)cu * 16) ^ ((uint32_t)(r & 7) << 4));
        CP_ASYNC16(dst, src);
    }
    stage_kv(hb + 16384, htid, b, 0);
    CP_COMMIT();
    CP_WAIT0();
    NB_SYNC(nbid);

    uint32_t qh[4][4], ql[4][4];
#pragma unroll
    for (int kk = 0; kk < 4; kk++) {
        uint32_t ra = hb + (uint32_t)(wh * 16 + rA) * 128
                    + (((uint32_t)(2*kk + uA) * 16) ^ swA);
        ldsm_x4(qh[kk], ra);
        ldsm_x4(ql[kk], ra + 8192);
    }

    float oA[8][4];
#pragma unroll
    for (int nd = 0; nd < 8; nd++)
#pragma unroll
        for (int i = 0; i < 4; i++) oA[nd][i] = 0.f;
    float m0r = -3.0e38f, m1r = -3.0e38f, l0r = 0.f, l1r = 0.f;

    for (int j = 0; j <= qt; j++) {
        if (j) { CP_WAIT0(); NB_SYNC(nbid); }
        const uint32_t buf = hb + 16384 + (uint32_t)(j & 1) * 32768;

        if (j < qt) {
            stage_kv(hb + 16384 + (uint32_t)((j + 1) & 1) * 32768, htid, b, (j + 1) * 64);
            CP_COMMIT();
        }

        // ---- S = Q . K^T : term-major issue, 8 indep accs per pass ----
        float sA[8][4];
#pragma unroll
        for (int nt = 0; nt < 8; nt++)
#pragma unroll
            for (int i = 0; i < 4; i++) sA[nt][i] = 0.f;
#pragma unroll
        for (int kk = 0; kk < 4; kk++) {
            uint32_t bh[8][2];
#pragma unroll
            for (int nt = 0; nt < 8; nt++) {
                uint32_t rb = buf + (uint32_t)(nt * 8 + rB) * 128
                            + (((uint32_t)(2*kk + uB) * 16) ^ swB);
                ldsm_x2(bh[nt], rb);
            }
#pragma unroll
            for (int nt = 0; nt < 8; nt++) mma16816(sA[nt], qh[kk], bh[nt]);
#pragma unroll
            for (int nt = 0; nt < 8; nt++) mma16816(sA[nt], ql[kk], bh[nt]);
            uint32_t bl[8][2];
#pragma unroll
            for (int nt = 0; nt < 8; nt++) {
                uint32_t rb = buf + 8192 + (uint32_t)(nt * 8 + rB) * 128
                            + (((uint32_t)(2*kk + uB) * 16) ^ swB);
                ldsm_x2(bl[nt], rb);
            }
#pragma unroll
            for (int nt = 0; nt < 8; nt++) mma16816(sA[nt], qh[kk], bl[nt]);
        }

        // ---- scale + causal mask ----
        if (j == qt) {
            const int r0 = qt * 64 + wh * 16 + gid, r1 = r0 + 8;
#pragma unroll
            for (int nt = 0; nt < 8; nt++) {
                int c0 = j * 64 + nt * 8 + 2 * tig;
                sA[nt][0] = (c0     <= r0) ? sA[nt][0] * 0.125f : -1e30f;
                sA[nt][1] = (c0 + 1 <= r0) ? sA[nt][1] * 0.125f : -1e30f;
                sA[nt][2] = (c0     <= r1) ? sA[nt][2] * 0.125f : -1e30f;
                sA[nt][3] = (c0 + 1 <= r1) ? sA[nt][3] * 0.125f : -1e30f;
            }
        } else {
#pragma unroll
            for (int nt = 0; nt < 8; nt++)
#pragma unroll
                for (int i = 0; i < 4; i++) sA[nt][i] *= 0.125f;
        }

        // ---- online softmax ----
        float mx0 = sA[0][0], mx1 = sA[0][2];
#pragma unroll
        for (int nt = 0; nt < 8; nt++) {
            mx0 = fmaxf(mx0, fmaxf(sA[nt][0], sA[nt][1]));
            mx1 = fmaxf(mx1, fmaxf(sA[nt][2], sA[nt][3]));
        }
        mx0 = fmaxf(mx0, __shfl_xor_sync(0xffffffffu, mx0, 1));
        mx0 = fmaxf(mx0, __shfl_xor_sync(0xffffffffu, mx0, 2));
        mx1 = fmaxf(mx1, __shfl_xor_sync(0xffffffffu, mx1, 1));
        mx1 = fmaxf(mx1, __shfl_xor_sync(0xffffffffu, mx1, 2));
        float mn0 = fmaxf(m0r, mx0), mn1 = fmaxf(m1r, mx1);
        float al0 = __expf(m0r - mn0), al1 = __expf(m1r - mn1);
        float ps0 = 0.f, ps1 = 0.f;
#pragma unroll
        for (int nt = 0; nt < 8; nt++) {
            sA[nt][0] = __expf(sA[nt][0] - mn0);
            sA[nt][1] = __expf(sA[nt][1] - mn0);
            sA[nt][2] = __expf(sA[nt][2] - mn1);
            sA[nt][3] = __expf(sA[nt][3] - mn1);
            ps0 += sA[nt][0] + sA[nt][1];
            ps1 += sA[nt][2] + sA[nt][3];
        }
        ps0 += __shfl_xor_sync(0xffffffffu, ps0, 1);
        ps0 += __shfl_xor_sync(0xffffffffu, ps0, 2);
        ps1 += __shfl_xor_sync(0xffffffffu, ps1, 1);
        ps1 += __shfl_xor_sync(0xffffffffu, ps1, 2);
        l0r = l0r * al0 + ps0;  m0r = mn0;
        l1r = l1r * al1 + ps1;  m1r = mn1;
#pragma unroll
        for (int nd = 0; nd < 8; nd++) {
            oA[nd][0] *= al0; oA[nd][1] *= al0;
            oA[nd][2] *= al1; oA[nd][3] *= al1;
        }

        // ---- PV: term-major issue ----
#pragma unroll
        for (int kk = 0; kk < 4; kk++) {
            uint32_t aphi[4], aplo[4];
            {
                __nv_bfloat16 h0,l0,h1,l1;
                split_bf16(sA[2*kk][0], h0, l0);   split_bf16(sA[2*kk][1], h1, l1);
                aphi[0] = pack_bf16x2(h0, h1);     aplo[0] = pack_bf16x2(l0, l1);
                split_bf16(sA[2*kk][2], h0, l0);   split_bf16(sA[2*kk][3], h1, l1);
                aphi[1] = pack_bf16x2(h0, h1);     aplo[1] = pack_bf16x2(l0, l1);
                split_bf16(sA[2*kk+1][0], h0, l0); split_bf16(sA[2*kk+1][1], h1, l1);
                aphi[2] = pack_bf16x2(h0, h1);     aplo[2] = pack_bf16x2(l0, l1);
                split_bf16(sA[2*kk+1][2], h0, l0); split_bf16(sA[2*kk+1][3], h1, l1);
                aphi[3] = pack_bf16x2(h0, h1);     aplo[3] = pack_bf16x2(l0, l1);
            }
            uint32_t vh[8][2];
#pragma unroll
            for (int nd = 0; nd < 8; nd++) {
                uint32_t rv = buf + 16384 + (uint32_t)(nd * 8 + rB) * 128
                            + (((uint32_t)(2*kk + uB) * 16) ^ swB);
                ldsm_x2(vh[nd], rv);
            }
#pragma unroll
            for (int nd = 0; nd < 8; nd++) mma16816(oA[nd], aphi, vh[nd]);
#pragma unroll
            for (int nd = 0; nd < 8; nd++) mma16816(oA[nd], aplo, vh[nd]);
            uint32_t vl[8][2];
#pragma unroll
            for (int nd = 0; nd < 8; nd++) {
                uint32_t rv = buf + 24576 + (uint32_t)(nd * 8 + rB) * 128
                            + (((uint32_t)(2*kk + uB) * 16) ^ swB);
                ldsm_x2(vl[nd], rv);
            }
#pragma unroll
            for (int nd = 0; nd < 8; nd++) mma16816(oA[nd], aphi, vl[nd]);
        }
    }

    const float inv0 = 1.f / l0r, inv1 = 1.f / l1r;
    const size_t out0 = ((size_t)b * TT + qt * 64 + wh * 16 + gid) * DD;
    const size_t out1 = out0 + 8 * DD;
#pragma unroll
    for (int nd = 0; nd < 8; nd++) {
        const int d0 = nd * 8 + 2 * tig;
        *(float2*)&out[out0 + d0] = make_float2(oA[nd][0] * inv0, oA[nd][1] * inv0);
        *(float2*)&out[out1 + d0] = make_float2(oA[nd][2] * inv1, oA[nd][3] * inv1);
    }
}

// ---------------------------------------------------------------------------
extern "C" void kernel_launch(void* const* d_in, const int* in_sizes, int n_in,
                              void* d_out, int out_size)
{
    const float* X  = (const float*)d_in[0];
    const float* Wq = (const float*)d_in[1];
    const float* bq = (const float*)d_in[2];
    const float* Wk = (const float*)d_in[3];
    const float* bk = (const float*)d_in[4];
    const float* Wv = (const float*)d_in[5];
    const float* bv = (const float*)d_in[6];
    float* out = (float*)d_out;

    x_prep<<<MM * 128 / 256, 256>>>(X);
    w_prep<<<16, 256>>>(Wq, Wk, Wv);

    cudaFuncSetAttribute(qkv_mma, cudaFuncAttributeMaxDynamicSharedMemorySize, QKV_SMEM);
    qkv_mma<<<MM / 64, 256, QKV_SMEM>>>(bq, bk, bv);

    cudaFuncSetAttribute(attn_mma, cudaFuncAttributeMaxDynamicSharedMemorySize, ATTN_SMEM);
    attn_mma<<<dim3(32, BB), 256, ATTN_SMEM>>>(out);
}